// round 1
// baseline (speedup 1.0000x reference)
#include <cuda_runtime.h>
#include <math.h>

// ---------------- problem constants ----------------
#define B_    16
#define T_    4000
#define GRUH  256
#define H1_   128
#define H2_   64
#define N_    320000          // T_ * HOP(80)
#define M_    (B_ * T_)       // 64000 tokens

// ---------------- device scratch (no allocs allowed) ----------------
__device__ float g_ratio[M_];
__device__ int   g_max_out_i;
__device__ int   g_max_enh_i;

__global__ void init_kernel() {
    g_max_out_i = 0;
    g_max_enh_i = 0;
}

// =====================================================================
// Kernel A: fused MLP  ratio[m] = clip(softplus(p2(m))+1, 1, 20)
//   X[64000,256] -> prelu(X W1^T+b1) -> prelu(. W2^T+b2) -> w3row2 dot
// 64 tokens per block, 256 threads, smem-tiled fp32 GEMM.
// =====================================================================
#define TM 64

// smem layout (floats):
//  [0 .. 2176)      Xs  [32][68]            (phase1, reused)
//  [2176 .. 6528)   Ws  [32][136]           (phase1, reused)
//  [0 .. 8704)      W2s [128][68]           (phase2, overlaps Xs/Ws)
//  [8704 .. 17408)  H1s [128][68]
//  [17408 .. 21760) H2s [64][68]
//  [21760 .. 21824) w3s [64]
#define SMEM_FLOATS 21824
#define SMEM_BYTES  (SMEM_FLOATS * 4)

__global__ __launch_bounds__(256, 2)
void mlp_kernel(const float* __restrict__ X,
                const float* __restrict__ W1, const float* __restrict__ b1,
                const float* __restrict__ a1p,
                const float* __restrict__ W2, const float* __restrict__ b2,
                const float* __restrict__ a2p,
                const float* __restrict__ W3, const float* __restrict__ b3)
{
    extern __shared__ float sm[];
    float* Xs  = sm;             // [32][68]
    float* Ws  = sm + 2176;      // [32][136]
    float* W2s = sm;             // [128][68]  (reuses Xs/Ws region)
    float* H1s = sm + 8704;      // [128][68]
    float* H2s = sm + 17408;     // [64][68]
    float* w3s = sm + 21760;     // [64]

    const int tid = threadIdx.x;
    const int tx  = tid & 15;    // 0..15
    const int ty  = tid >> 4;    // 0..15
    const int m0  = blockIdx.x * TM;

    // ---------------- phase 1: H1 = prelu(X W1^T + b1) ----------------
    float acc[4][8];
    #pragma unroll
    for (int i = 0; i < 4; ++i)
        #pragma unroll
        for (int j = 0; j < 8; ++j) acc[i][j] = 0.0f;

    #pragma unroll 1
    for (int kt = 0; kt < 8; ++kt) {
        const int k0 = kt * 32;
        // load X tile transposed: Xs[k][tok]
        {
            const int tok = tid >> 2;          // 0..63
            const int kq  = (tid & 3) * 8;     // 0,8,16,24
            const float* src = X + (size_t)(m0 + tok) * GRUH + k0 + kq;
            float4 v0 = *(const float4*)(src);
            float4 v1 = *(const float4*)(src + 4);
            Xs[(kq + 0) * 68 + tok] = v0.x;
            Xs[(kq + 1) * 68 + tok] = v0.y;
            Xs[(kq + 2) * 68 + tok] = v0.z;
            Xs[(kq + 3) * 68 + tok] = v0.w;
            Xs[(kq + 4) * 68 + tok] = v1.x;
            Xs[(kq + 5) * 68 + tok] = v1.y;
            Xs[(kq + 6) * 68 + tok] = v1.z;
            Xs[(kq + 7) * 68 + tok] = v1.w;
        }
        // load W1 tile transposed: Ws[k][c]
        {
            const int c  = tid >> 1;           // 0..127
            const int kq = (tid & 1) * 16;     // 0,16
            const float* src = W1 + (size_t)c * GRUH + k0 + kq;
            #pragma unroll
            for (int u = 0; u < 4; ++u) {
                float4 v = *(const float4*)(src + u * 4);
                Ws[(kq + u * 4 + 0) * 136 + c] = v.x;
                Ws[(kq + u * 4 + 1) * 136 + c] = v.y;
                Ws[(kq + u * 4 + 2) * 136 + c] = v.z;
                Ws[(kq + u * 4 + 3) * 136 + c] = v.w;
            }
        }
        __syncthreads();
        #pragma unroll
        for (int k = 0; k < 32; ++k) {
            float4 a  = *(float4*)&Xs[k * 68 + ty * 4];
            float4 bA = *(float4*)&Ws[k * 136 + tx * 8];
            float4 bB = *(float4*)&Ws[k * 136 + tx * 8 + 4];
            float av[4] = {a.x, a.y, a.z, a.w};
            float bv[8] = {bA.x, bA.y, bA.z, bA.w, bB.x, bB.y, bB.z, bB.w};
            #pragma unroll
            for (int i = 0; i < 4; ++i)
                #pragma unroll
                for (int j = 0; j < 8; ++j)
                    acc[i][j] = fmaf(av[i], bv[j], acc[i][j]);
        }
        __syncthreads();
    }

    // bias + prelu -> H1s[c][tok]
    {
        const float A1 = *a1p;
        #pragma unroll
        for (int j = 0; j < 8; ++j) {
            const int c = tx * 8 + j;
            const float bb = b1[c];
            #pragma unroll
            for (int i = 0; i < 4; ++i) {
                float v = acc[i][j] + bb;
                v = (v >= 0.0f) ? v : A1 * v;
                H1s[c * 68 + ty * 4 + i] = v;
            }
        }
    }
    if (tid < 64) w3s[tid] = W3[2 * H2_ + tid];
    __syncthreads();

    // ---------------- phase 2: H2 = prelu(H1 W2^T + b2) ----------------
    // load W2 transposed: W2s[k][c]
    {
        const int c  = tid >> 2;               // 0..63
        const int kq = (tid & 3) * 32;         // 0,32,64,96
        const float* src = W2 + (size_t)c * H1_ + kq;
        #pragma unroll
        for (int u = 0; u < 8; ++u) {
            float4 v = *(const float4*)(src + u * 4);
            W2s[(kq + u * 4 + 0) * 68 + c] = v.x;
            W2s[(kq + u * 4 + 1) * 68 + c] = v.y;
            W2s[(kq + u * 4 + 2) * 68 + c] = v.z;
            W2s[(kq + u * 4 + 3) * 68 + c] = v.w;
        }
    }
    __syncthreads();

    float acc2[4][4];
    #pragma unroll
    for (int i = 0; i < 4; ++i)
        #pragma unroll
        for (int j = 0; j < 4; ++j) acc2[i][j] = 0.0f;

    #pragma unroll 8
    for (int k = 0; k < 128; ++k) {
        float4 a = *(float4*)&H1s[k * 68 + ty * 4];
        float4 b = *(float4*)&W2s[k * 68 + tx * 4];
        float av[4] = {a.x, a.y, a.z, a.w};
        float bv[4] = {b.x, b.y, b.z, b.w};
        #pragma unroll
        for (int i = 0; i < 4; ++i)
            #pragma unroll
            for (int j = 0; j < 4; ++j)
                acc2[i][j] = fmaf(av[i], bv[j], acc2[i][j]);
    }
    {
        const float A2 = *a2p;
        #pragma unroll
        for (int j = 0; j < 4; ++j) {
            const int c = tx * 4 + j;
            const float bb = b2[c];
            #pragma unroll
            for (int i = 0; i < 4; ++i) {
                float v = acc2[i][j] + bb;
                v = (v >= 0.0f) ? v : A2 * v;
                H2s[c * 68 + ty * 4 + i] = v;
            }
        }
    }
    __syncthreads();

    // ---------------- phase 3: p2 -> ratio ----------------
    if (tid < TM) {
        const int tok = tid;
        float p = b3[2];
        #pragma unroll 16
        for (int k = 0; k < 64; ++k)
            p = fmaf(H2s[k * 68 + tok], w3s[k], p);
        // stable softplus matching jax.nn.softplus
        float sp = fmaxf(p, 0.0f) + log1pf(expf(-fabsf(p)));
        float ratio = sp + 1.0f;
        ratio = fminf(fmaxf(ratio, 1.0f), 20.0f);
        g_ratio[m0 + tok] = ratio;
    }
}

// =====================================================================
// Kernel B: interp ratio, compute gains, warp-parallel IIR scan,
//           combine, write out_pre, track global maxima.
// =====================================================================
#define CHUNK 1280
#define WARM  256
#define CPB   (N_ / CHUNK)    // 250 chunks per batch

__device__ __forceinline__ float interp_ratio(const float* __restrict__ rb, int n)
{
    float src = ((float)n + 0.5f) * 0.0125f - 0.5f;   // T/N = 1/80 exactly
    src = fminf(fmaxf(src, 0.0f), 3999.0f);
    float f0 = floorf(src);
    int   i0 = (int)f0;
    int   i1 = min(i0 + 1, 3999);
    float w  = src - f0;
    float r0 = rb[i0];
    float r1 = rb[i1];
    return r0 * (1.0f - w) + r1 * w;
}

__device__ __forceinline__ float gain_of(float x, float thr, float ratio)
{
    float env = fabsf(x);
    float gr  = (env > thr) ? (thr + (env - thr) / ratio) : env;
    float g   = gr / (env + 1e-8f);
    return fminf(fmaxf(g, 0.1f), 2.0f);
}

// inclusive scan of v with weights 0.9^(distance), in-warp (5 steps)
__device__ __forceinline__ float iir_scan(float v, int lane)
{
    float t;
    t = __shfl_up_sync(0xffffffffu, v, 1);  if (lane >= 1)  v = fmaf(0.9f,                 t, v);
    t = __shfl_up_sync(0xffffffffu, v, 2);  if (lane >= 2)  v = fmaf(0.81f,                t, v);
    t = __shfl_up_sync(0xffffffffu, v, 4);  if (lane >= 4)  v = fmaf(0.6561f,              t, v);
    t = __shfl_up_sync(0xffffffffu, v, 8);  if (lane >= 8)  v = fmaf(0.43046721f,          t, v);
    t = __shfl_up_sync(0xffffffffu, v, 16); if (lane >= 16) v = fmaf(0.18530201888518416f, t, v);
    return v;
}

__global__ __launch_bounds__(256)
void compress_kernel(const float* __restrict__ enh,
                     const float* __restrict__ noisy,
                     float* __restrict__ out)
{
    const int w    = (blockIdx.x * blockDim.x + threadIdx.x) >> 5;
    const int lane = threadIdx.x & 31;
    const int b     = w / CPB;
    const int chunk = w % CPB;
    const int t0    = chunk * CHUNK;
    const int start = (chunk == 0) ? 0 : (t0 - WARM);

    const float* eb = enh   + (size_t)b * N_;
    const float* nb = noisy + (size_t)b * N_;
    float*       ob = out   + (size_t)b * N_;
    const float* rb = g_ratio + b * T_;

    const float rp = powf(0.9f, (float)(lane + 1));   // 0.9^(lane+1)

    // init carry: s = gain at first sample of the window
    float s_e, s_r;
    {
        float e  = eb[start];
        float nn = nb[start];
        float ratio = interp_ratio(rb, start);
        s_e = gain_of(e, 0.3f, ratio);
        s_r = gain_of(nn - e, 0.1f, ratio * 0.5f);
    }

    float mx_out = 0.0f, mx_enh = 0.0f;
    const int nend = t0 + CHUNK;

    for (int g0 = start; g0 < nend; g0 += 32) {
        const int n = g0 + lane;
        float e   = eb[n];
        float nn  = nb[n];
        float res = nn - e;
        float ratio = interp_ratio(rb, n);
        float ge = gain_of(e,   0.3f, ratio);
        float gr = gain_of(res, 0.1f, ratio * 0.5f);

        float ve = iir_scan(0.1f * ge, lane);
        float vr = iir_scan(0.1f * gr, lane);
        float se = fmaf(rp, s_e, ve);
        float sr = fmaf(rp, s_r, vr);
        s_e = __shfl_sync(0xffffffffu, se, 31);
        s_r = __shfl_sync(0xffffffffu, sr, 31);

        if (g0 >= t0) {
            float o = fmaf(se, e, 0.1f * (sr * res));
            ob[n] = o;
            mx_out = fmaxf(mx_out, fabsf(o));
            mx_enh = fmaxf(mx_enh, fabsf(e));
        }
    }

    #pragma unroll
    for (int off = 16; off > 0; off >>= 1) {
        mx_out = fmaxf(mx_out, __shfl_xor_sync(0xffffffffu, mx_out, off));
        mx_enh = fmaxf(mx_enh, __shfl_xor_sync(0xffffffffu, mx_enh, off));
    }
    if (lane == 0) {
        atomicMax(&g_max_out_i, __float_as_int(mx_out));   // non-negative floats: int order == float order
        atomicMax(&g_max_enh_i, __float_as_int(mx_enh));
    }
}

// =====================================================================
// Kernel C: in-place normalize  out *= max_enh / (max_out + 1e-8)
// =====================================================================
__global__ __launch_bounds__(256)
void scale_kernel(float* __restrict__ out)
{
    const float mo = __int_as_float(g_max_out_i);
    const float me = __int_as_float(g_max_enh_i);
    const float s  = me / (mo + 1e-8f);
    const int i = blockIdx.x * blockDim.x + threadIdx.x;
    const int n4 = (B_ * N_) / 4;
    if (i < n4) {
        float4* o4 = (float4*)out;
        float4 v = o4[i];
        v.x *= s; v.y *= s; v.z *= s; v.w *= s;
        o4[i] = v;
    }
}

// =====================================================================
extern "C" void kernel_launch(void* const* d_in, const int* in_sizes, int n_in,
                              void* d_out, int out_size)
{
    const float* gru   = (const float*)d_in[0];
    const float* enh   = (const float*)d_in[1];
    const float* noisy = (const float*)d_in[2];
    const float* W1    = (const float*)d_in[3];
    const float* b1    = (const float*)d_in[4];
    const float* a1    = (const float*)d_in[5];
    const float* W2    = (const float*)d_in[6];
    const float* b2    = (const float*)d_in[7];
    const float* a2    = (const float*)d_in[8];
    const float* W3    = (const float*)d_in[9];
    const float* b3    = (const float*)d_in[10];
    float* out = (float*)d_out;

    cudaFuncSetAttribute(mlp_kernel, cudaFuncAttributeMaxDynamicSharedMemorySize, SMEM_BYTES);

    init_kernel<<<1, 1>>>();
    mlp_kernel<<<M_ / TM, 256, SMEM_BYTES>>>(gru, W1, b1, a1, W2, b2, a2, W3, b3);
    compress_kernel<<<(B_ * CPB) / 8, 256>>>(enh, noisy, out);       // 4000 warps
    scale_kernel<<<((B_ * N_ / 4) + 255) / 256, 256>>>(out);
}

// round 3
// speedup vs baseline: 1.7744x; 1.7744x over previous
#include <cuda_runtime.h>
#include <cuda_bf16.h>
#include <math.h>
#include <stdint.h>

// ---------------- problem constants ----------------
#define B_    16
#define T_    4000
#define GRUH  256
#define H1_   128
#define H2_   64
#define N_    320000          // T_ * HOP(80)
#define M_    (B_ * T_)       // 64000 tokens

// ---------------- device scratch ----------------
__device__ float g_ratio[M_];
__device__ int   g_max_out_i;
__device__ int   g_max_enh_i;

// =====================================================================
// helpers
// =====================================================================
__device__ __forceinline__ uint32_t pack_bf16x2(__nv_bfloat16 a, __nv_bfloat16 b) {
    return (uint32_t)__bfloat16_as_ushort(a) | ((uint32_t)__bfloat16_as_ushort(b) << 16);
}
__device__ __forceinline__ void split2(float v0, float v1, uint32_t& hi, uint32_t& lo) {
    __nv_bfloat16 h0 = __float2bfloat16_rn(v0);
    __nv_bfloat16 h1 = __float2bfloat16_rn(v1);
    float l0 = v0 - __bfloat162float(h0);
    float l1 = v1 - __bfloat162float(h1);
    hi = pack_bf16x2(h0, h1);
    lo = pack_bf16x2(__float2bfloat16_rn(l0), __float2bfloat16_rn(l1));
}
// m16n8k16 bf16 MMA, f32 accumulate (portable PTX, sm_80+)
__device__ __forceinline__ void mma_bf16(float c[4], const uint32_t a[4],
                                         uint32_t b0, uint32_t b1) {
    asm volatile(
        "mma.sync.aligned.m16n8k16.row.col.f32.bf16.bf16.f32 "
        "{%0,%1,%2,%3}, {%4,%5,%6,%7}, {%8,%9}, {%0,%1,%2,%3};"
        : "+f"(c[0]), "+f"(c[1]), "+f"(c[2]), "+f"(c[3])
        : "r"(a[0]), "r"(a[1]), "r"(a[2]), "r"(a[3]), "r"(b0), "r"(b1));
}

// =====================================================================
// Kernel A: fused split-bf16 MLP via mma.sync  ->  ratio[m]
//   128 tokens/CTA, 500 CTAs, 256 threads (8 warps x 16 rows)
// =====================================================================
#define TOK 128

// smem byte offsets
// W1 (hi/lo) rows padded to 264 ushorts; W2/H1 rows padded to 136 ushorts.
#define SO_W1H  0          // 128*264*2 = 67584
#define SO_W1L  67584      // 67584
#define SO_H1H  0          // reuses W1H region after GEMM1 (34816 B)
#define SO_H1L  36864      // 34816 B, still inside old W1 region
#define SO_W2H  135168     // 64*136*2 = 17408
#define SO_W2L  152576     // 17408
#define SO_B1   169984     // 128 f
#define SO_B2   170496     // 64 f
#define SO_W3   170752     // 64 f
#define SO_SC   171008     // a1, a2, b3[2]
#define MLP_SMEM 171040

#define W1_STRIDE_W 132    // uint32 words per W1 row (264 ushorts)
#define W2_STRIDE_W 68     // uint32 words per W2/H1 row (136 ushorts)

__global__ __launch_bounds__(256, 1)
void mlp_mma_kernel(const float* __restrict__ X,
                    const float* __restrict__ W1, const float* __restrict__ b1,
                    const float* __restrict__ a1p,
                    const float* __restrict__ W2, const float* __restrict__ b2,
                    const float* __restrict__ a2p,
                    const float* __restrict__ W3, const float* __restrict__ b3)
{
    extern __shared__ char sm[];
    const int tid  = threadIdx.x;
    const int wid  = tid >> 5;
    const int lane = tid & 31;
    const int grp  = lane >> 2;   // 0..7
    const int tig  = lane & 3;    // 0..3
    const int m0   = blockIdx.x * TOK;

    uint32_t* w1h = (uint32_t*)(sm + SO_W1H);
    uint32_t* w1l = (uint32_t*)(sm + SO_W1L);
    uint32_t* w2h = (uint32_t*)(sm + SO_W2H);
    uint32_t* w2l = (uint32_t*)(sm + SO_W2L);
    uint32_t* h1h = (uint32_t*)(sm + SO_H1H);
    uint32_t* h1l = (uint32_t*)(sm + SO_H1L);
    float* b1s = (float*)(sm + SO_B1);
    float* b2s = (float*)(sm + SO_B2);
    float* w3s = (float*)(sm + SO_W3);
    float* scl = (float*)(sm + SO_SC);

    if (blockIdx.x == 0 && tid == 0) { g_max_out_i = 0; g_max_enh_i = 0; }

    // ---- stage biases / w3 row 2 / scalars ----
    if (tid < 128) b1s[tid] = b1[tid];
    else if (tid < 192) b2s[tid - 128] = b2[tid - 128];
    else w3s[tid - 192] = W3[2 * H2_ + (tid - 192)];
    if (tid == 0) { scl[0] = *a1p; scl[1] = *a2p; scl[2] = b3[2]; }

    // ---- stage W1 -> smem hi/lo bf16, layout [n][k], padded rows ----
    {
        const int row = tid >> 1;              // 0..127 (output channel n)
        const int cb  = (tid & 1) * 128;       // k half
        const float4* src = (const float4*)(W1 + (size_t)row * GRUH + cb);
        uint32_t* dh = w1h + row * W1_STRIDE_W + cb / 2;
        uint32_t* dl = w1l + row * W1_STRIDE_W + cb / 2;
        #pragma unroll 8
        for (int u = 0; u < 32; ++u) {
            float4 v = src[u];
            uint32_t h0, l0, h1, l1;
            split2(v.x, v.y, h0, l0);
            split2(v.z, v.w, h1, l1);
            dh[2 * u] = h0; dh[2 * u + 1] = h1;
            dl[2 * u] = l0; dl[2 * u + 1] = l1;
        }
    }
    // ---- stage W2 -> smem hi/lo, [n][k] padded ----
    {
        const int row = tid >> 2;              // 0..63
        const int cb  = (tid & 3) * 32;        // k quarter
        const float4* src = (const float4*)(W2 + (size_t)row * H1_ + cb);
        uint32_t* dh = w2h + row * W2_STRIDE_W + cb / 2;
        uint32_t* dl = w2l + row * W2_STRIDE_W + cb / 2;
        #pragma unroll
        for (int u = 0; u < 8; ++u) {
            float4 v = src[u];
            uint32_t h0, l0, h1, l1;
            split2(v.x, v.y, h0, l0);
            split2(v.z, v.w, h1, l1);
            dh[2 * u] = h0; dh[2 * u + 1] = h1;
            dl[2 * u] = l0; dl[2 * u + 1] = l1;
        }
    }
    __syncthreads();

    // =================== GEMM1: [128 x 256] * W1^T -> [128 x 128] ===================
    const float* xr0 = X + (size_t)(m0 + wid * 16 + grp) * GRUH;
    const float* xr8 = xr0 + 8 * GRUH;

    float acc[16][4];
    #pragma unroll
    for (int nt = 0; nt < 16; ++nt)
        #pragma unroll
        for (int j = 0; j < 4; ++j) acc[nt][j] = 0.0f;

    #pragma unroll 1
    for (int kt = 0; kt < 16; ++kt) {
        const int k0 = kt * 16 + tig * 2;
        float2 x00 = *(const float2*)(xr0 + k0);
        float2 x10 = *(const float2*)(xr8 + k0);
        float2 x01 = *(const float2*)(xr0 + k0 + 8);
        float2 x11 = *(const float2*)(xr8 + k0 + 8);
        uint32_t ah[4], al[4];
        split2(x00.x, x00.y, ah[0], al[0]);
        split2(x10.x, x10.y, ah[1], al[1]);
        split2(x01.x, x01.y, ah[2], al[2]);
        split2(x11.x, x11.y, ah[3], al[3]);

        const int wbase = kt * 8 + tig;
        #pragma unroll
        for (int nt = 0; nt < 16; ++nt) {
            const int n = nt * 8 + grp;
            const uint32_t* ph = w1h + n * W1_STRIDE_W + wbase;
            const uint32_t* pl = w1l + n * W1_STRIDE_W + wbase;
            uint32_t bh0 = ph[0], bh1 = ph[4];
            uint32_t bl0 = pl[0], bl1 = pl[4];
            mma_bf16(acc[nt], ah, bh0, bh1);
            mma_bf16(acc[nt], ah, bl0, bl1);
            mma_bf16(acc[nt], al, bh0, bh1);
        }
    }
    __syncthreads();   // all warps finished reading W1 smem

    // ---- epilogue 1: bias + prelu, split hi/lo -> H1 smem (over old W1) ----
    {
        const float A1 = scl[0];
        const int r  = wid * 16 + grp;
        #pragma unroll
        for (int nt = 0; nt < 16; ++nt) {
            const int col0 = nt * 8 + tig * 2;
            float v00 = acc[nt][0] + b1s[col0];
            float v01 = acc[nt][1] + b1s[col0 + 1];
            float v80 = acc[nt][2] + b1s[col0];
            float v81 = acc[nt][3] + b1s[col0 + 1];
            v00 = (v00 >= 0.0f) ? v00 : A1 * v00;
            v01 = (v01 >= 0.0f) ? v01 : A1 * v01;
            v80 = (v80 >= 0.0f) ? v80 : A1 * v80;
            v81 = (v81 >= 0.0f) ? v81 : A1 * v81;
            uint32_t h0, l0, h8, l8;
            split2(v00, v01, h0, l0);
            split2(v80, v81, h8, l8);
            const int w0 = r * W2_STRIDE_W + nt * 4 + tig;
            const int w8 = (r + 8) * W2_STRIDE_W + nt * 4 + tig;
            h1h[w0] = h0; h1l[w0] = l0;
            h1h[w8] = h8; h1l[w8] = l8;
        }
    }
    __syncthreads();

    // =================== GEMM2: [128 x 128] * W2^T -> [128 x 64] ===================
    float acc2[8][4];
    #pragma unroll
    for (int nt = 0; nt < 8; ++nt)
        #pragma unroll
        for (int j = 0; j < 4; ++j) acc2[nt][j] = 0.0f;

    const int r0w = (wid * 16 + grp) * W2_STRIDE_W;
    const int r8w = (wid * 16 + grp + 8) * W2_STRIDE_W;

    #pragma unroll 1
    for (int kt = 0; kt < 8; ++kt) {
        const int wbase = kt * 8 + tig;
        uint32_t ah[4], al[4];
        ah[0] = h1h[r0w + wbase];     al[0] = h1l[r0w + wbase];
        ah[1] = h1h[r8w + wbase];     al[1] = h1l[r8w + wbase];
        ah[2] = h1h[r0w + wbase + 4]; al[2] = h1l[r0w + wbase + 4];
        ah[3] = h1h[r8w + wbase + 4]; al[3] = h1l[r8w + wbase + 4];
        #pragma unroll
        for (int nt = 0; nt < 8; ++nt) {
            const int n = nt * 8 + grp;
            const uint32_t* ph = w2h + n * W2_STRIDE_W + wbase;
            const uint32_t* pl = w2l + n * W2_STRIDE_W + wbase;
            uint32_t bh0 = ph[0], bh1 = ph[4];
            uint32_t bl0 = pl[0], bl1 = pl[4];
            mma_bf16(acc2[nt], ah, bh0, bh1);
            mma_bf16(acc2[nt], ah, bl0, bl1);
            mma_bf16(acc2[nt], al, bh0, bh1);
        }
    }

    // ---- epilogue 2: bias + prelu, dot w3, reduce over tig, softplus ----
    {
        const float A2 = scl[1];
        float p0 = 0.0f, p8 = 0.0f;
        #pragma unroll
        for (int nt = 0; nt < 8; ++nt) {
            const int col0 = nt * 8 + tig * 2;
            float v00 = acc2[nt][0] + b2s[col0];
            float v01 = acc2[nt][1] + b2s[col0 + 1];
            float v80 = acc2[nt][2] + b2s[col0];
            float v81 = acc2[nt][3] + b2s[col0 + 1];
            v00 = (v00 >= 0.0f) ? v00 : A2 * v00;
            v01 = (v01 >= 0.0f) ? v01 : A2 * v01;
            v80 = (v80 >= 0.0f) ? v80 : A2 * v80;
            v81 = (v81 >= 0.0f) ? v81 : A2 * v81;
            p0 = fmaf(v00, w3s[col0], fmaf(v01, w3s[col0 + 1], p0));
            p8 = fmaf(v80, w3s[col0], fmaf(v81, w3s[col0 + 1], p8));
        }
        p0 += __shfl_xor_sync(0xffffffffu, p0, 1);
        p0 += __shfl_xor_sync(0xffffffffu, p0, 2);
        p8 += __shfl_xor_sync(0xffffffffu, p8, 1);
        p8 += __shfl_xor_sync(0xffffffffu, p8, 2);
        if (tig == 0) {
            const float bb3 = scl[2];
            float pa = p0 + bb3;
            float pb = p8 + bb3;
            float spa = fmaxf(pa, 0.0f) + log1pf(expf(-fabsf(pa)));
            float spb = fmaxf(pb, 0.0f) + log1pf(expf(-fabsf(pb)));
            float ra = fminf(fmaxf(spa + 1.0f, 1.0f), 20.0f);
            float rb = fminf(fmaxf(spb + 1.0f, 1.0f), 20.0f);
            g_ratio[m0 + wid * 16 + grp]     = ra;
            g_ratio[m0 + wid * 16 + grp + 8] = rb;
        }
    }
}

// =====================================================================
// Kernel B: compressor (warp-parallel IIR scan) — unchanged
// =====================================================================
#define CHUNK 1280
#define WARM  256
#define CPB   (N_ / CHUNK)

__device__ __forceinline__ float interp_ratio(const float* __restrict__ rb, int n)
{
    float src = ((float)n + 0.5f) * 0.0125f - 0.5f;
    src = fminf(fmaxf(src, 0.0f), 3999.0f);
    float f0 = floorf(src);
    int   i0 = (int)f0;
    int   i1 = min(i0 + 1, 3999);
    float w  = src - f0;
    return rb[i0] * (1.0f - w) + rb[i1] * w;
}
__device__ __forceinline__ float gain_of(float x, float thr, float ratio)
{
    float env = fabsf(x);
    float gr  = (env > thr) ? (thr + (env - thr) / ratio) : env;
    float g   = gr / (env + 1e-8f);
    return fminf(fmaxf(g, 0.1f), 2.0f);
}
__device__ __forceinline__ float iir_scan(float v, int lane)
{
    float t;
    t = __shfl_up_sync(0xffffffffu, v, 1);  if (lane >= 1)  v = fmaf(0.9f,                 t, v);
    t = __shfl_up_sync(0xffffffffu, v, 2);  if (lane >= 2)  v = fmaf(0.81f,                t, v);
    t = __shfl_up_sync(0xffffffffu, v, 4);  if (lane >= 4)  v = fmaf(0.6561f,              t, v);
    t = __shfl_up_sync(0xffffffffu, v, 8);  if (lane >= 8)  v = fmaf(0.43046721f,          t, v);
    t = __shfl_up_sync(0xffffffffu, v, 16); if (lane >= 16) v = fmaf(0.18530201888518416f, t, v);
    return v;
}

__global__ __launch_bounds__(256)
void compress_kernel(const float* __restrict__ enh,
                     const float* __restrict__ noisy,
                     float* __restrict__ out)
{
    const int w    = (blockIdx.x * blockDim.x + threadIdx.x) >> 5;
    const int lane = threadIdx.x & 31;
    const int b     = w / CPB;
    const int chunk = w % CPB;
    const int t0    = chunk * CHUNK;
    const int start = (chunk == 0) ? 0 : (t0 - WARM);

    const float* eb = enh   + (size_t)b * N_;
    const float* nb = noisy + (size_t)b * N_;
    float*       ob = out   + (size_t)b * N_;
    const float* rb = g_ratio + b * T_;

    const float rp = powf(0.9f, (float)(lane + 1));

    float s_e, s_r;
    {
        float e  = eb[start];
        float nn = nb[start];
        float ratio = interp_ratio(rb, start);
        s_e = gain_of(e, 0.3f, ratio);
        s_r = gain_of(nn - e, 0.1f, ratio * 0.5f);
    }

    float mx_out = 0.0f, mx_enh = 0.0f;
    const int nend = t0 + CHUNK;

    for (int g0 = start; g0 < nend; g0 += 32) {
        const int n = g0 + lane;
        float e   = eb[n];
        float nn  = nb[n];
        float res = nn - e;
        float ratio = interp_ratio(rb, n);
        float ge = gain_of(e,   0.3f, ratio);
        float gr = gain_of(res, 0.1f, ratio * 0.5f);

        float ve = iir_scan(0.1f * ge, lane);
        float vr = iir_scan(0.1f * gr, lane);
        float se = fmaf(rp, s_e, ve);
        float sr = fmaf(rp, s_r, vr);
        s_e = __shfl_sync(0xffffffffu, se, 31);
        s_r = __shfl_sync(0xffffffffu, sr, 31);

        if (g0 >= t0) {
            float o = fmaf(se, e, 0.1f * (sr * res));
            ob[n] = o;
            mx_out = fmaxf(mx_out, fabsf(o));
            mx_enh = fmaxf(mx_enh, fabsf(e));
        }
    }

    #pragma unroll
    for (int off = 16; off > 0; off >>= 1) {
        mx_out = fmaxf(mx_out, __shfl_xor_sync(0xffffffffu, mx_out, off));
        mx_enh = fmaxf(mx_enh, __shfl_xor_sync(0xffffffffu, mx_enh, off));
    }
    if (lane == 0) {
        atomicMax(&g_max_out_i, __float_as_int(mx_out));
        atomicMax(&g_max_enh_i, __float_as_int(mx_enh));
    }
}

// =====================================================================
// Kernel C: normalize
// =====================================================================
__global__ __launch_bounds__(256)
void scale_kernel(float* __restrict__ out)
{
    const float mo = __int_as_float(g_max_out_i);
    const float me = __int_as_float(g_max_enh_i);
    const float s  = me / (mo + 1e-8f);
    const int i = blockIdx.x * blockDim.x + threadIdx.x;
    const int n4 = (B_ * N_) / 4;
    if (i < n4) {
        float4* o4 = (float4*)out;
        float4 v = o4[i];
        v.x *= s; v.y *= s; v.z *= s; v.w *= s;
        o4[i] = v;
    }
}

// =====================================================================
extern "C" void kernel_launch(void* const* d_in, const int* in_sizes, int n_in,
                              void* d_out, int out_size)
{
    const float* gru   = (const float*)d_in[0];
    const float* enh   = (const float*)d_in[1];
    const float* noisy = (const float*)d_in[2];
    const float* W1    = (const float*)d_in[3];
    const float* b1    = (const float*)d_in[4];
    const float* a1    = (const float*)d_in[5];
    const float* W2    = (const float*)d_in[6];
    const float* b2    = (const float*)d_in[7];
    const float* a2    = (const float*)d_in[8];
    const float* W3    = (const float*)d_in[9];
    const float* b3    = (const float*)d_in[10];
    float* out = (float*)d_out;

    cudaFuncSetAttribute(mlp_mma_kernel, cudaFuncAttributeMaxDynamicSharedMemorySize, MLP_SMEM);

    mlp_mma_kernel<<<M_ / TOK, 256, MLP_SMEM>>>(gru, W1, b1, a1, W2, b2, a2, W3, b3);
    compress_kernel<<<(B_ * CPB) / 8, 256>>>(enh, noisy, out);
    scale_kernel<<<((B_ * N_ / 4) + 255) / 256, 256>>>(out);
}

// round 5
// speedup vs baseline: 2.1003x; 1.1837x over previous
#include <cuda_runtime.h>
#include <cuda_bf16.h>
#include <math.h>
#include <stdint.h>

// ---------------- problem constants ----------------
#define B_    16
#define T_    4000
#define GRUH  256
#define H1_   128
#define H2_   64
#define N_    320000          // T_ * HOP(80)
#define M_    (B_ * T_)       // 64000 tokens

// ---------------- device scratch ----------------
__device__ float g_ratio[M_];
__device__ int   g_max_out_i;
__device__ int   g_max_enh_i;

// =====================================================================
// helpers
// =====================================================================
__device__ __forceinline__ uint32_t pack_bf16x2(__nv_bfloat16 a, __nv_bfloat16 b) {
    return (uint32_t)__bfloat16_as_ushort(a) | ((uint32_t)__bfloat16_as_ushort(b) << 16);
}
__device__ __forceinline__ void split2(float v0, float v1, uint32_t& hi, uint32_t& lo) {
    __nv_bfloat16 h0 = __float2bfloat16_rn(v0);
    __nv_bfloat16 h1 = __float2bfloat16_rn(v1);
    float l0 = v0 - __bfloat162float(h0);
    float l1 = v1 - __bfloat162float(h1);
    hi = pack_bf16x2(h0, h1);
    lo = pack_bf16x2(__float2bfloat16_rn(l0), __float2bfloat16_rn(l1));
}
// m16n8k16 bf16 MMA, f32 accumulate (portable PTX, sm_80+)
__device__ __forceinline__ void mma_bf16_(float c[4], const uint32_t a[4],
                                          uint32_t b0, uint32_t b1) {
    asm volatile(
        "mma.sync.aligned.m16n8k16.row.col.f32.bf16.bf16.f32 "
        "{%0,%1,%2,%3}, {%4,%5,%6,%7}, {%8,%9}, {%0,%1,%2,%3};"
        : "+f"(c[0]), "+f"(c[1]), "+f"(c[2]), "+f"(c[3])
        : "r"(a[0]), "r"(a[1]), "r"(a[2]), "r"(a[3]), "r"(b0), "r"(b1));
}
#define MMA(c, a, b0, b1) mma_bf16_(c, a, b0, b1)

// =====================================================================
// Kernel A: fused split-bf16 MLP via mma.sync  ->  ratio[m]
//   256 tokens/CTA, 250 CTAs, 512 threads (16 warps x 16 rows)
// B-operands stored as 16B granules {bh0,bh1,bl0,bl1}: one LDS.128
// per (n, kt) serves all three MMA products. Row stride in granules is
// ≡ 4 (mod 8) (68 / 36) => 8 consecutive lanes hit 8 distinct bank
// groups (conflict-free 128-bit LDS).
// =====================================================================
#define TOK 256

#define W1_GSTRIDE 68      // granules (16B) per W1 row  (64 data + 4 pad)
#define W2_GSTRIDE 36      // granules per W2 row        (32 data + 4 pad)
#define H1_WSTRIDE 68      // uint32 words per H1 row

// smem byte offsets
#define SO_W2Q  0                              // 64*36*16   = 36864
#define SO_B1   36864                          // 128 f
#define SO_B2   37376                          // 64 f
#define SO_W3   37632                          // 64 f
#define SO_SC   37888                          // scalars
#define SO_W1Q  38016                          // 128*68*16  = 139264 -> end 177280
#define SO_H1H  38016                          // 256*68*4   = 69632  (overlaps dead W1)
#define SO_H1L  107648                         // 69632 -> end 177280
#define MLP_SMEM 177280

__global__ __launch_bounds__(512, 1)
void mlp_mma_kernel(const float* __restrict__ X,
                    const float* __restrict__ W1, const float* __restrict__ b1,
                    const float* __restrict__ a1p,
                    const float* __restrict__ W2, const float* __restrict__ b2,
                    const float* __restrict__ a2p,
                    const float* __restrict__ W3, const float* __restrict__ b3)
{
    extern __shared__ char sm[];
    const int tid  = threadIdx.x;
    const int wid  = tid >> 5;    // 0..15
    const int lane = tid & 31;
    const int grp  = lane >> 2;   // 0..7
    const int tig  = lane & 3;    // 0..3
    const int m0   = blockIdx.x * TOK;

    uint4* w1q = (uint4*)(sm + SO_W1Q);
    uint4* w2q = (uint4*)(sm + SO_W2Q);
    uint32_t* h1h = (uint32_t*)(sm + SO_H1H);
    uint32_t* h1l = (uint32_t*)(sm + SO_H1L);
    float* b1s = (float*)(sm + SO_B1);
    float* b2s = (float*)(sm + SO_B2);
    float* w3s = (float*)(sm + SO_W3);
    float* scl = (float*)(sm + SO_SC);

    if (blockIdx.x == 0 && tid == 0) { g_max_out_i = 0; g_max_enh_i = 0; }

    // ---- stage biases / w3 row 2 / scalars ----
    if (tid < 128) b1s[tid] = b1[tid];
    else if (tid < 192) b2s[tid - 128] = b2[tid - 128];
    else if (tid < 256) w3s[tid - 192] = W3[2 * H2_ + (tid - 192)];
    if (tid == 0) { scl[0] = *a1p; scl[1] = *a2p; scl[2] = b3[2]; }

    // ---- stage W1 -> interleaved hi/lo granules ----
    {
        const int row = tid >> 2;          // 0..127
        const int q   = tid & 3;           // kt quarter
        const float* src = W1 + (size_t)row * GRUH;
        #pragma unroll
        for (int kk = 0; kk < 4; ++kk) {
            const int kt = q * 4 + kk;
            const float4* s4 = (const float4*)(src + kt * 16);
            float4 f0 = s4[0], f1 = s4[1], f2 = s4[2], f3 = s4[3];
            uint32_t h[8], l[8];
            split2(f0.x, f0.y, h[0], l[0]); split2(f0.z, f0.w, h[1], l[1]);
            split2(f1.x, f1.y, h[2], l[2]); split2(f1.z, f1.w, h[3], l[3]);
            split2(f2.x, f2.y, h[4], l[4]); split2(f2.z, f2.w, h[5], l[5]);
            split2(f3.x, f3.y, h[6], l[6]); split2(f3.z, f3.w, h[7], l[7]);
            uint4* g = w1q + row * W1_GSTRIDE + kt * 4;
            #pragma unroll
            for (int t = 0; t < 4; ++t)
                g[t] = make_uint4(h[t], h[t + 4], l[t], l[t + 4]);
        }
    }
    // ---- stage W2 -> interleaved granules ----
    {
        const int row = tid >> 3;          // 0..63
        const int kt  = tid & 7;           // 0..7
        const float4* s4 = (const float4*)(W2 + (size_t)row * H1_ + kt * 16);
        float4 f0 = s4[0], f1 = s4[1], f2 = s4[2], f3 = s4[3];
        uint32_t h[8], l[8];
        split2(f0.x, f0.y, h[0], l[0]); split2(f0.z, f0.w, h[1], l[1]);
        split2(f1.x, f1.y, h[2], l[2]); split2(f1.z, f1.w, h[3], l[3]);
        split2(f2.x, f2.y, h[4], l[4]); split2(f2.z, f2.w, h[5], l[5]);
        split2(f3.x, f3.y, h[6], l[6]); split2(f3.z, f3.w, h[7], l[7]);
        uint4* g = w2q + row * W2_GSTRIDE + kt * 4;
        #pragma unroll
        for (int t = 0; t < 4; ++t)
            g[t] = make_uint4(h[t], h[t + 4], l[t], l[t + 4]);
    }
    __syncthreads();

    // =================== GEMM1: [256 x 256] * W1^T -> [256 x 128] ===================
    const float* xr0 = X + (size_t)(m0 + wid * 16 + grp) * GRUH;
    const float* xr8 = xr0 + 8 * GRUH;

    float acc[16][4];
    #pragma unroll
    for (int nt = 0; nt < 16; ++nt)
        #pragma unroll
        for (int j = 0; j < 4; ++j) acc[nt][j] = 0.0f;

    #pragma unroll 1
    for (int kt = 0; kt < 16; ++kt) {
        const int k0 = kt * 16 + tig * 2;
        float2 x00 = *(const float2*)(xr0 + k0);
        float2 x10 = *(const float2*)(xr8 + k0);
        float2 x01 = *(const float2*)(xr0 + k0 + 8);
        float2 x11 = *(const float2*)(xr8 + k0 + 8);
        uint32_t ah[4], al[4];
        split2(x00.x, x00.y, ah[0], al[0]);
        split2(x10.x, x10.y, ah[1], al[1]);
        split2(x01.x, x01.y, ah[2], al[2]);
        split2(x11.x, x11.y, ah[3], al[3]);

        const uint4* p = w1q + grp * W1_GSTRIDE + kt * 4 + tig;
        #pragma unroll
        for (int nt = 0; nt < 16; ++nt) {
            uint4 g = *p;
            p += 8 * W1_GSTRIDE;
            MMA(acc[nt], ah, g.x, g.y);
            MMA(acc[nt], ah, g.z, g.w);
            MMA(acc[nt], al, g.x, g.y);
        }
    }
    __syncthreads();   // all warps finished reading W1 smem

    // ---- epilogue 1: bias + prelu, split hi/lo -> H1 smem (over old W1) ----
    {
        const float A1 = scl[0];
        const int r = wid * 16 + grp;
        #pragma unroll
        for (int nt = 0; nt < 16; ++nt) {
            const int col0 = nt * 8 + tig * 2;
            float v00 = acc[nt][0] + b1s[col0];
            float v01 = acc[nt][1] + b1s[col0 + 1];
            float v80 = acc[nt][2] + b1s[col0];
            float v81 = acc[nt][3] + b1s[col0 + 1];
            v00 = (v00 >= 0.0f) ? v00 : A1 * v00;
            v01 = (v01 >= 0.0f) ? v01 : A1 * v01;
            v80 = (v80 >= 0.0f) ? v80 : A1 * v80;
            v81 = (v81 >= 0.0f) ? v81 : A1 * v81;
            uint32_t h0, l0, h8, l8;
            split2(v00, v01, h0, l0);
            split2(v80, v81, h8, l8);
            const int w0 = r * H1_WSTRIDE + nt * 4 + tig;
            const int w8 = (r + 8) * H1_WSTRIDE + nt * 4 + tig;
            h1h[w0] = h0; h1l[w0] = l0;
            h1h[w8] = h8; h1l[w8] = l8;
        }
    }
    __syncthreads();

    // =================== GEMM2: [256 x 128] * W2^T -> [256 x 64] ===================
    float acc2[8][4];
    #pragma unroll
    for (int nt = 0; nt < 8; ++nt)
        #pragma unroll
        for (int j = 0; j < 4; ++j) acc2[nt][j] = 0.0f;

    const int r0w = (wid * 16 + grp) * H1_WSTRIDE;
    const int r8w = (wid * 16 + grp + 8) * H1_WSTRIDE;

    #pragma unroll 1
    for (int kt = 0; kt < 8; ++kt) {
        const int wbase = kt * 8 + tig;
        uint32_t ah[4], al[4];
        ah[0] = h1h[r0w + wbase];     al[0] = h1l[r0w + wbase];
        ah[1] = h1h[r8w + wbase];     al[1] = h1l[r8w + wbase];
        ah[2] = h1h[r0w + wbase + 4]; al[2] = h1l[r0w + wbase + 4];
        ah[3] = h1h[r8w + wbase + 4]; al[3] = h1l[r8w + wbase + 4];
        const uint4* p = w2q + grp * W2_GSTRIDE + kt * 4 + tig;
        #pragma unroll
        for (int nt = 0; nt < 8; ++nt) {
            uint4 g = *p;
            p += 8 * W2_GSTRIDE;
            MMA(acc2[nt], ah, g.x, g.y);
            MMA(acc2[nt], ah, g.z, g.w);
            MMA(acc2[nt], al, g.x, g.y);
        }
    }

    // ---- epilogue 2: bias + prelu, dot w3, reduce over tig, softplus ----
    {
        const float A2 = scl[1];
        float p0 = 0.0f, p8 = 0.0f;
        #pragma unroll
        for (int nt = 0; nt < 8; ++nt) {
            const int col0 = nt * 8 + tig * 2;
            float v00 = acc2[nt][0] + b2s[col0];
            float v01 = acc2[nt][1] + b2s[col0 + 1];
            float v80 = acc2[nt][2] + b2s[col0];
            float v81 = acc2[nt][3] + b2s[col0 + 1];
            v00 = (v00 >= 0.0f) ? v00 : A2 * v00;
            v01 = (v01 >= 0.0f) ? v01 : A2 * v01;
            v80 = (v80 >= 0.0f) ? v80 : A2 * v80;
            v81 = (v81 >= 0.0f) ? v81 : A2 * v81;
            p0 = fmaf(v00, w3s[col0], fmaf(v01, w3s[col0 + 1], p0));
            p8 = fmaf(v80, w3s[col0], fmaf(v81, w3s[col0 + 1], p8));
        }
        p0 += __shfl_xor_sync(0xffffffffu, p0, 1);
        p0 += __shfl_xor_sync(0xffffffffu, p0, 2);
        p8 += __shfl_xor_sync(0xffffffffu, p8, 1);
        p8 += __shfl_xor_sync(0xffffffffu, p8, 2);
        if (tig == 0) {
            const float bb3 = scl[2];
            float pa = p0 + bb3;
            float pb = p8 + bb3;
            float spa = fmaxf(pa, 0.0f) + log1pf(expf(-fabsf(pa)));
            float spb = fmaxf(pb, 0.0f) + log1pf(expf(-fabsf(pb)));
            float ra = fminf(fmaxf(spa + 1.0f, 1.0f), 20.0f);
            float rb = fminf(fmaxf(spb + 1.0f, 1.0f), 20.0f);
            g_ratio[m0 + wid * 16 + grp]     = ra;
            g_ratio[m0 + wid * 16 + grp + 8] = rb;
        }
    }
}

// =====================================================================
// Kernel B: compressor (warp-parallel IIR scan) — unchanged
// =====================================================================
#define CHUNK 1280
#define WARM  256
#define CPB   (N_ / CHUNK)

__device__ __forceinline__ float interp_ratio(const float* __restrict__ rb, int n)
{
    float src = ((float)n + 0.5f) * 0.0125f - 0.5f;
    src = fminf(fmaxf(src, 0.0f), 3999.0f);
    float f0 = floorf(src);
    int   i0 = (int)f0;
    int   i1 = min(i0 + 1, 3999);
    float w  = src - f0;
    return rb[i0] * (1.0f - w) + rb[i1] * w;
}
__device__ __forceinline__ float gain_of(float x, float thr, float ratio)
{
    float env = fabsf(x);
    float gr  = (env > thr) ? (thr + (env - thr) / ratio) : env;
    float g   = gr / (env + 1e-8f);
    return fminf(fmaxf(g, 0.1f), 2.0f);
}
__device__ __forceinline__ float iir_scan(float v, int lane)
{
    float t;
    t = __shfl_up_sync(0xffffffffu, v, 1);  if (lane >= 1)  v = fmaf(0.9f,                 t, v);
    t = __shfl_up_sync(0xffffffffu, v, 2);  if (lane >= 2)  v = fmaf(0.81f,                t, v);
    t = __shfl_up_sync(0xffffffffu, v, 4);  if (lane >= 4)  v = fmaf(0.6561f,              t, v);
    t = __shfl_up_sync(0xffffffffu, v, 8);  if (lane >= 8)  v = fmaf(0.43046721f,          t, v);
    t = __shfl_up_sync(0xffffffffu, v, 16); if (lane >= 16) v = fmaf(0.18530201888518416f, t, v);
    return v;
}

__global__ __launch_bounds__(256)
void compress_kernel(const float* __restrict__ enh,
                     const float* __restrict__ noisy,
                     float* __restrict__ out)
{
    const int w    = (blockIdx.x * blockDim.x + threadIdx.x) >> 5;
    const int lane = threadIdx.x & 31;
    const int b     = w / CPB;
    const int chunk = w % CPB;
    const int t0    = chunk * CHUNK;
    const int start = (chunk == 0) ? 0 : (t0 - WARM);

    const float* eb = enh   + (size_t)b * N_;
    const float* nb = noisy + (size_t)b * N_;
    float*       ob = out   + (size_t)b * N_;
    const float* rb = g_ratio + b * T_;

    const float rp = powf(0.9f, (float)(lane + 1));

    float s_e, s_r;
    {
        float e  = eb[start];
        float nn = nb[start];
        float ratio = interp_ratio(rb, start);
        s_e = gain_of(e, 0.3f, ratio);
        s_r = gain_of(nn - e, 0.1f, ratio * 0.5f);
    }

    float mx_out = 0.0f, mx_enh = 0.0f;
    const int nend = t0 + CHUNK;

    for (int g0 = start; g0 < nend; g0 += 32) {
        const int n = g0 + lane;
        float e   = eb[n];
        float nn  = nb[n];
        float res = nn - e;
        float ratio = interp_ratio(rb, n);
        float ge = gain_of(e,   0.3f, ratio);
        float gr = gain_of(res, 0.1f, ratio * 0.5f);

        float ve = iir_scan(0.1f * ge, lane);
        float vr = iir_scan(0.1f * gr, lane);
        float se = fmaf(rp, s_e, ve);
        float sr = fmaf(rp, s_r, vr);
        s_e = __shfl_sync(0xffffffffu, se, 31);
        s_r = __shfl_sync(0xffffffffu, sr, 31);

        if (g0 >= t0) {
            float o = fmaf(se, e, 0.1f * (sr * res));
            ob[n] = o;
            mx_out = fmaxf(mx_out, fabsf(o));
            mx_enh = fmaxf(mx_enh, fabsf(e));
        }
    }

    #pragma unroll
    for (int off = 16; off > 0; off >>= 1) {
        mx_out = fmaxf(mx_out, __shfl_xor_sync(0xffffffffu, mx_out, off));
        mx_enh = fmaxf(mx_enh, __shfl_xor_sync(0xffffffffu, mx_enh, off));
    }
    if (lane == 0) {
        atomicMax(&g_max_out_i, __float_as_int(mx_out));
        atomicMax(&g_max_enh_i, __float_as_int(mx_enh));
    }
}

// =====================================================================
// Kernel C: normalize
// =====================================================================
__global__ __launch_bounds__(256)
void scale_kernel(float* __restrict__ out)
{
    const float mo = __int_as_float(g_max_out_i);
    const float me = __int_as_float(g_max_enh_i);
    const float s  = me / (mo + 1e-8f);
    const int i = blockIdx.x * blockDim.x + threadIdx.x;
    const int n4 = (B_ * N_) / 4;
    if (i < n4) {
        float4* o4 = (float4*)out;
        float4 v = o4[i];
        v.x *= s; v.y *= s; v.z *= s; v.w *= s;
        o4[i] = v;
    }
}

// =====================================================================
extern "C" void kernel_launch(void* const* d_in, const int* in_sizes, int n_in,
                              void* d_out, int out_size)
{
    const float* gru   = (const float*)d_in[0];
    const float* enh   = (const float*)d_in[1];
    const float* noisy = (const float*)d_in[2];
    const float* W1    = (const float*)d_in[3];
    const float* b1    = (const float*)d_in[4];
    const float* a1    = (const float*)d_in[5];
    const float* W2    = (const float*)d_in[6];
    const float* b2    = (const float*)d_in[7];
    const float* a2    = (const float*)d_in[8];
    const float* W3    = (const float*)d_in[9];
    const float* b3    = (const float*)d_in[10];
    float* out = (float*)d_out;

    cudaFuncSetAttribute(mlp_mma_kernel, cudaFuncAttributeMaxDynamicSharedMemorySize, MLP_SMEM);

    mlp_mma_kernel<<<M_ / TOK, 512, MLP_SMEM>>>(gru, W1, b1, a1, W2, b2, a2, W3, b3);
    compress_kernel<<<(B_ * CPB) / 8, 256>>>(enh, noisy, out);
    scale_kernel<<<((B_ * N_ / 4) + 255) / 256, 256>>>(out);
}

// round 6
// speedup vs baseline: 2.1624x; 1.0296x over previous
#include <cuda_runtime.h>
#include <cuda_bf16.h>
#include <math.h>
#include <stdint.h>

// ---------------- problem constants ----------------
#define B_    16
#define T_    4000
#define GRUH  256
#define H1_   128
#define H2_   64
#define N_    320000          // T_ * HOP(80)
#define M_    (B_ * T_)       // 64000 tokens

// ---------------- device scratch ----------------
__device__ float g_ratio[M_];
__device__ int   g_max_out_i;
__device__ int   g_max_enh_i;

// =====================================================================
// helpers
// =====================================================================
__device__ __forceinline__ uint32_t pack_bf16x2(__nv_bfloat16 a, __nv_bfloat16 b) {
    return (uint32_t)__bfloat16_as_ushort(a) | ((uint32_t)__bfloat16_as_ushort(b) << 16);
}
__device__ __forceinline__ void split2(float v0, float v1, uint32_t& hi, uint32_t& lo) {
    __nv_bfloat16 h0 = __float2bfloat16_rn(v0);
    __nv_bfloat16 h1 = __float2bfloat16_rn(v1);
    float l0 = v0 - __bfloat162float(h0);
    float l1 = v1 - __bfloat162float(h1);
    hi = pack_bf16x2(h0, h1);
    lo = pack_bf16x2(__float2bfloat16_rn(l0), __float2bfloat16_rn(l1));
}
// m16n8k16 bf16 MMA, f32 accumulate (portable PTX, sm_80+)
__device__ __forceinline__ void mma_bf16_(float c[4], const uint32_t a[4],
                                          uint32_t b0, uint32_t b1) {
    asm volatile(
        "mma.sync.aligned.m16n8k16.row.col.f32.bf16.bf16.f32 "
        "{%0,%1,%2,%3}, {%4,%5,%6,%7}, {%8,%9}, {%0,%1,%2,%3};"
        : "+f"(c[0]), "+f"(c[1]), "+f"(c[2]), "+f"(c[3])
        : "r"(a[0]), "r"(a[1]), "r"(a[2]), "r"(a[3]), "r"(b0), "r"(b1));
}
#define MMA(c, a, b0, b1) mma_bf16_(c, a, b0, b1)

// =====================================================================
// Kernel A: fused split-bf16 MLP via mma.sync  ->  ratio[m]
//   256 tokens/CTA, 250 CTAs, 512 threads.
//   GEMM1 warp mapping: 16 warps = 8 M-groups (32 rows = two m16 tiles)
//   x 2 N-halves (64 cols). Each B granule (one LDS.128, {bh0,bh1,bl0,bl1})
//   now feeds 6 MMAs (2 m-tiles x 3 split-products) -> half the LDS issue
//   of R5, denser tensor-pipe feeding. A (X rows) prefetched one kt ahead.
// =====================================================================
#define TOK 256

#define W1_GSTRIDE 68      // granules (16B) per W1 row  (64 data + 4 pad)
#define W2_GSTRIDE 36      // granules per W2 row        (32 data + 4 pad)
#define H1_WSTRIDE 68      // uint32 words per H1 row

// smem byte offsets
#define SO_W2Q  0                              // 64*36*16   = 36864
#define SO_B1   36864                          // 128 f
#define SO_B2   37376                          // 64 f
#define SO_W3   37632                          // 64 f
#define SO_SC   37888                          // scalars
#define SO_W1Q  38016                          // 128*68*16  = 139264 -> end 177280
#define SO_H1H  38016                          // 256*68*4   = 69632  (overlaps dead W1)
#define SO_H1L  107648                         // 69632 -> end 177280
#define MLP_SMEM 177280

__global__ __launch_bounds__(512, 1)
void mlp_mma_kernel(const float* __restrict__ X,
                    const float* __restrict__ W1, const float* __restrict__ b1,
                    const float* __restrict__ a1p,
                    const float* __restrict__ W2, const float* __restrict__ b2,
                    const float* __restrict__ a2p,
                    const float* __restrict__ W3, const float* __restrict__ b3)
{
    extern __shared__ char sm[];
    const int tid  = threadIdx.x;
    const int wid  = tid >> 5;    // 0..15
    const int lane = tid & 31;
    const int grp  = lane >> 2;   // 0..7
    const int tig  = lane & 3;    // 0..3
    const int m0   = blockIdx.x * TOK;

    uint4* w1q = (uint4*)(sm + SO_W1Q);
    uint4* w2q = (uint4*)(sm + SO_W2Q);
    uint32_t* h1h = (uint32_t*)(sm + SO_H1H);
    uint32_t* h1l = (uint32_t*)(sm + SO_H1L);
    float* b1s = (float*)(sm + SO_B1);
    float* b2s = (float*)(sm + SO_B2);
    float* w3s = (float*)(sm + SO_W3);
    float* scl = (float*)(sm + SO_SC);

    if (blockIdx.x == 0 && tid == 0) { g_max_out_i = 0; g_max_enh_i = 0; }

    // ---- stage biases / w3 row 2 / scalars ----
    if (tid < 128) b1s[tid] = b1[tid];
    else if (tid < 192) b2s[tid - 128] = b2[tid - 128];
    else if (tid < 256) w3s[tid - 192] = W3[2 * H2_ + (tid - 192)];
    if (tid == 0) { scl[0] = *a1p; scl[1] = *a2p; scl[2] = b3[2]; }

    // ---- stage W1 -> interleaved hi/lo granules ----
    {
        const int row = tid >> 2;          // 0..127
        const int q   = tid & 3;           // kt quarter
        const float* src = W1 + (size_t)row * GRUH;
        #pragma unroll
        for (int kk = 0; kk < 4; ++kk) {
            const int kt = q * 4 + kk;
            const float4* s4 = (const float4*)(src + kt * 16);
            float4 f0 = s4[0], f1 = s4[1], f2 = s4[2], f3 = s4[3];
            uint32_t h[8], l[8];
            split2(f0.x, f0.y, h[0], l[0]); split2(f0.z, f0.w, h[1], l[1]);
            split2(f1.x, f1.y, h[2], l[2]); split2(f1.z, f1.w, h[3], l[3]);
            split2(f2.x, f2.y, h[4], l[4]); split2(f2.z, f2.w, h[5], l[5]);
            split2(f3.x, f3.y, h[6], l[6]); split2(f3.z, f3.w, h[7], l[7]);
            uint4* g = w1q + row * W1_GSTRIDE + kt * 4;
            #pragma unroll
            for (int t = 0; t < 4; ++t)
                g[t] = make_uint4(h[t], h[t + 4], l[t], l[t + 4]);
        }
    }
    // ---- stage W2 -> interleaved granules ----
    {
        const int row = tid >> 3;          // 0..63
        const int kt  = tid & 7;           // 0..7
        const float4* s4 = (const float4*)(W2 + (size_t)row * H1_ + kt * 16);
        float4 f0 = s4[0], f1 = s4[1], f2 = s4[2], f3 = s4[3];
        uint32_t h[8], l[8];
        split2(f0.x, f0.y, h[0], l[0]); split2(f0.z, f0.w, h[1], l[1]);
        split2(f1.x, f1.y, h[2], l[2]); split2(f1.z, f1.w, h[3], l[3]);
        split2(f2.x, f2.y, h[4], l[4]); split2(f2.z, f2.w, h[5], l[5]);
        split2(f3.x, f3.y, h[6], l[6]); split2(f3.z, f3.w, h[7], l[7]);
        uint4* g = w2q + row * W2_GSTRIDE + kt * 4;
        #pragma unroll
        for (int t = 0; t < 4; ++t)
            g[t] = make_uint4(h[t], h[t + 4], l[t], l[t + 4]);
    }
    __syncthreads();

    // ========= GEMM1: [256 x 256] * W1^T -> [256 x 128] =========
    // warp = (wid_m, nhalf): rows wid_m*32 + {grp, grp+8, grp+16, grp+24},
    // cols nhalf*64 .. +64
    const int wid_m  = wid >> 1;
    const int nhalf  = wid & 1;
    const float* xr0  = X + (size_t)(m0 + wid_m * 32 + grp) * GRUH;
    const float* xr8  = xr0 + 8  * GRUH;
    const float* xr16 = xr0 + 16 * GRUH;
    const float* xr24 = xr0 + 24 * GRUH;

    float acc[2][8][4];
    #pragma unroll
    for (int t = 0; t < 2; ++t)
        #pragma unroll
        for (int nt = 0; nt < 8; ++nt)
            #pragma unroll
            for (int j = 0; j < 4; ++j) acc[t][nt][j] = 0.0f;

    // preload kt = 0
    float2 c00, c10, c20, c30, c01, c11, c21, c31;
    {
        const int k0 = tig * 2;
        c00 = *(const float2*)(xr0  + k0);  c01 = *(const float2*)(xr0  + k0 + 8);
        c10 = *(const float2*)(xr8  + k0);  c11 = *(const float2*)(xr8  + k0 + 8);
        c20 = *(const float2*)(xr16 + k0);  c21 = *(const float2*)(xr16 + k0 + 8);
        c30 = *(const float2*)(xr24 + k0);  c31 = *(const float2*)(xr24 + k0 + 8);
    }

    #pragma unroll 1
    for (int kt = 0; kt < 16; ++kt) {
        uint32_t ah0[4], al0[4], ah1[4], al1[4];
        split2(c00.x, c00.y, ah0[0], al0[0]);
        split2(c10.x, c10.y, ah0[1], al0[1]);
        split2(c01.x, c01.y, ah0[2], al0[2]);
        split2(c11.x, c11.y, ah0[3], al0[3]);
        split2(c20.x, c20.y, ah1[0], al1[0]);
        split2(c30.x, c30.y, ah1[1], al1[1]);
        split2(c21.x, c21.y, ah1[2], al1[2]);
        split2(c31.x, c31.y, ah1[3], al1[3]);

        // prefetch next kt (clamped; redundant re-read on last iter)
        {
            const int ktn = (kt < 15) ? kt + 1 : 15;
            const int k0 = ktn * 16 + tig * 2;
            c00 = *(const float2*)(xr0  + k0);  c01 = *(const float2*)(xr0  + k0 + 8);
            c10 = *(const float2*)(xr8  + k0);  c11 = *(const float2*)(xr8  + k0 + 8);
            c20 = *(const float2*)(xr16 + k0);  c21 = *(const float2*)(xr16 + k0 + 8);
            c30 = *(const float2*)(xr24 + k0);  c31 = *(const float2*)(xr24 + k0 + 8);
        }

        const uint4* p = w1q + (nhalf * 64 + grp) * W1_GSTRIDE + kt * 4 + tig;
        #pragma unroll
        for (int nt = 0; nt < 8; ++nt) {
            uint4 g = *p;
            p += 8 * W1_GSTRIDE;
            MMA(acc[0][nt], ah0, g.x, g.y);
            MMA(acc[0][nt], ah0, g.z, g.w);
            MMA(acc[0][nt], al0, g.x, g.y);
            MMA(acc[1][nt], ah1, g.x, g.y);
            MMA(acc[1][nt], ah1, g.z, g.w);
            MMA(acc[1][nt], al1, g.x, g.y);
        }
    }
    __syncthreads();   // all warps finished reading W1 smem

    // ---- epilogue 1: bias + prelu, split hi/lo -> H1 smem (over old W1) ----
    {
        const float A1 = scl[0];
        const int rbase = wid_m * 32 + grp;
        #pragma unroll
        for (int t = 0; t < 2; ++t) {
            const int r = rbase + t * 16;
            #pragma unroll
            for (int nt = 0; nt < 8; ++nt) {
                const int col0 = nhalf * 64 + nt * 8 + tig * 2;
                float v00 = acc[t][nt][0] + b1s[col0];
                float v01 = acc[t][nt][1] + b1s[col0 + 1];
                float v80 = acc[t][nt][2] + b1s[col0];
                float v81 = acc[t][nt][3] + b1s[col0 + 1];
                v00 = (v00 >= 0.0f) ? v00 : A1 * v00;
                v01 = (v01 >= 0.0f) ? v01 : A1 * v01;
                v80 = (v80 >= 0.0f) ? v80 : A1 * v80;
                v81 = (v81 >= 0.0f) ? v81 : A1 * v81;
                uint32_t h0, l0, h8, l8;
                split2(v00, v01, h0, l0);
                split2(v80, v81, h8, l8);
                const int cw = nhalf * 32 + nt * 4 + tig;
                const int w0 = r * H1_WSTRIDE + cw;
                const int w8 = (r + 8) * H1_WSTRIDE + cw;
                h1h[w0] = h0; h1l[w0] = l0;
                h1h[w8] = h8; h1l[w8] = l8;
            }
        }
    }
    __syncthreads();

    // ========= GEMM2: [256 x 128] * W2^T -> [256 x 64] =========
    float acc2[8][4];
    #pragma unroll
    for (int nt = 0; nt < 8; ++nt)
        #pragma unroll
        for (int j = 0; j < 4; ++j) acc2[nt][j] = 0.0f;

    const int r0w = (wid * 16 + grp) * H1_WSTRIDE;
    const int r8w = (wid * 16 + grp + 8) * H1_WSTRIDE;

    #pragma unroll 1
    for (int kt = 0; kt < 8; ++kt) {
        const int wbase = kt * 8 + tig;
        uint32_t ah[4], al[4];
        ah[0] = h1h[r0w + wbase];     al[0] = h1l[r0w + wbase];
        ah[1] = h1h[r8w + wbase];     al[1] = h1l[r8w + wbase];
        ah[2] = h1h[r0w + wbase + 4]; al[2] = h1l[r0w + wbase + 4];
        ah[3] = h1h[r8w + wbase + 4]; al[3] = h1l[r8w + wbase + 4];
        const uint4* p = w2q + grp * W2_GSTRIDE + kt * 4 + tig;
        #pragma unroll
        for (int nt = 0; nt < 8; ++nt) {
            uint4 g = *p;
            p += 8 * W2_GSTRIDE;
            MMA(acc2[nt], ah, g.x, g.y);
            MMA(acc2[nt], ah, g.z, g.w);
            MMA(acc2[nt], al, g.x, g.y);
        }
    }

    // ---- epilogue 2: bias + prelu, dot w3, reduce over tig, softplus ----
    {
        const float A2 = scl[1];
        float p0 = 0.0f, p8 = 0.0f;
        #pragma unroll
        for (int nt = 0; nt < 8; ++nt) {
            const int col0 = nt * 8 + tig * 2;
            float v00 = acc2[nt][0] + b2s[col0];
            float v01 = acc2[nt][1] + b2s[col0 + 1];
            float v80 = acc2[nt][2] + b2s[col0];
            float v81 = acc2[nt][3] + b2s[col0 + 1];
            v00 = (v00 >= 0.0f) ? v00 : A2 * v00;
            v01 = (v01 >= 0.0f) ? v01 : A2 * v01;
            v80 = (v80 >= 0.0f) ? v80 : A2 * v80;
            v81 = (v81 >= 0.0f) ? v81 : A2 * v81;
            p0 = fmaf(v00, w3s[col0], fmaf(v01, w3s[col0 + 1], p0));
            p8 = fmaf(v80, w3s[col0], fmaf(v81, w3s[col0 + 1], p8));
        }
        p0 += __shfl_xor_sync(0xffffffffu, p0, 1);
        p0 += __shfl_xor_sync(0xffffffffu, p0, 2);
        p8 += __shfl_xor_sync(0xffffffffu, p8, 1);
        p8 += __shfl_xor_sync(0xffffffffu, p8, 2);
        if (tig == 0) {
            const float bb3 = scl[2];
            float pa = p0 + bb3;
            float pb = p8 + bb3;
            float spa = fmaxf(pa, 0.0f) + log1pf(expf(-fabsf(pa)));
            float spb = fmaxf(pb, 0.0f) + log1pf(expf(-fabsf(pb)));
            float ra = fminf(fmaxf(spa + 1.0f, 1.0f), 20.0f);
            float rb = fminf(fmaxf(spb + 1.0f, 1.0f), 20.0f);
            g_ratio[m0 + wid * 16 + grp]     = ra;
            g_ratio[m0 + wid * 16 + grp + 8] = rb;
        }
    }
}

// =====================================================================
// Kernel B: compressor (warp-parallel IIR scan) — unchanged
// =====================================================================
#define CHUNK 1280
#define WARM  256
#define CPB   (N_ / CHUNK)

__device__ __forceinline__ float interp_ratio(const float* __restrict__ rb, int n)
{
    float src = ((float)n + 0.5f) * 0.0125f - 0.5f;
    src = fminf(fmaxf(src, 0.0f), 3999.0f);
    float f0 = floorf(src);
    int   i0 = (int)f0;
    int   i1 = min(i0 + 1, 3999);
    float w  = src - f0;
    return rb[i0] * (1.0f - w) + rb[i1] * w;
}
__device__ __forceinline__ float gain_of(float x, float thr, float ratio)
{
    float env = fabsf(x);
    float gr  = (env > thr) ? (thr + (env - thr) / ratio) : env;
    float g   = gr / (env + 1e-8f);
    return fminf(fmaxf(g, 0.1f), 2.0f);
}
__device__ __forceinline__ float iir_scan(float v, int lane)
{
    float t;
    t = __shfl_up_sync(0xffffffffu, v, 1);  if (lane >= 1)  v = fmaf(0.9f,                 t, v);
    t = __shfl_up_sync(0xffffffffu, v, 2);  if (lane >= 2)  v = fmaf(0.81f,                t, v);
    t = __shfl_up_sync(0xffffffffu, v, 4);  if (lane >= 4)  v = fmaf(0.6561f,              t, v);
    t = __shfl_up_sync(0xffffffffu, v, 8);  if (lane >= 8)  v = fmaf(0.43046721f,          t, v);
    t = __shfl_up_sync(0xffffffffu, v, 16); if (lane >= 16) v = fmaf(0.18530201888518416f, t, v);
    return v;
}

__global__ __launch_bounds__(256)
void compress_kernel(const float* __restrict__ enh,
                     const float* __restrict__ noisy,
                     float* __restrict__ out)
{
    const int w    = (blockIdx.x * blockDim.x + threadIdx.x) >> 5;
    const int lane = threadIdx.x & 31;
    const int b     = w / CPB;
    const int chunk = w % CPB;
    const int t0    = chunk * CHUNK;
    const int start = (chunk == 0) ? 0 : (t0 - WARM);

    const float* eb = enh   + (size_t)b * N_;
    const float* nb = noisy + (size_t)b * N_;
    float*       ob = out   + (size_t)b * N_;
    const float* rb = g_ratio + b * T_;

    const float rp = powf(0.9f, (float)(lane + 1));

    float s_e, s_r;
    {
        float e  = eb[start];
        float nn = nb[start];
        float ratio = interp_ratio(rb, start);
        s_e = gain_of(e, 0.3f, ratio);
        s_r = gain_of(nn - e, 0.1f, ratio * 0.5f);
    }

    float mx_out = 0.0f, mx_enh = 0.0f;
    const int nend = t0 + CHUNK;

    for (int g0 = start; g0 < nend; g0 += 32) {
        const int n = g0 + lane;
        float e   = eb[n];
        float nn  = nb[n];
        float res = nn - e;
        float ratio = interp_ratio(rb, n);
        float ge = gain_of(e,   0.3f, ratio);
        float gr = gain_of(res, 0.1f, ratio * 0.5f);

        float ve = iir_scan(0.1f * ge, lane);
        float vr = iir_scan(0.1f * gr, lane);
        float se = fmaf(rp, s_e, ve);
        float sr = fmaf(rp, s_r, vr);
        s_e = __shfl_sync(0xffffffffu, se, 31);
        s_r = __shfl_sync(0xffffffffu, sr, 31);

        if (g0 >= t0) {
            float o = fmaf(se, e, 0.1f * (sr * res));
            ob[n] = o;
            mx_out = fmaxf(mx_out, fabsf(o));
            mx_enh = fmaxf(mx_enh, fabsf(e));
        }
    }

    #pragma unroll
    for (int off = 16; off > 0; off >>= 1) {
        mx_out = fmaxf(mx_out, __shfl_xor_sync(0xffffffffu, mx_out, off));
        mx_enh = fmaxf(mx_enh, __shfl_xor_sync(0xffffffffu, mx_enh, off));
    }
    if (lane == 0) {
        atomicMax(&g_max_out_i, __float_as_int(mx_out));
        atomicMax(&g_max_enh_i, __float_as_int(mx_enh));
    }
}

// =====================================================================
// Kernel C: normalize
// =====================================================================
__global__ __launch_bounds__(256)
void scale_kernel(float* __restrict__ out)
{
    const float mo = __int_as_float(g_max_out_i);
    const float me = __int_as_float(g_max_enh_i);
    const float s  = me / (mo + 1e-8f);
    const int i = blockIdx.x * blockDim.x + threadIdx.x;
    const int n4 = (B_ * N_) / 4;
    if (i < n4) {
        float4* o4 = (float4*)out;
        float4 v = o4[i];
        v.x *= s; v.y *= s; v.z *= s; v.w *= s;
        o4[i] = v;
    }
}

// =====================================================================
extern "C" void kernel_launch(void* const* d_in, const int* in_sizes, int n_in,
                              void* d_out, int out_size)
{
    const float* gru   = (const float*)d_in[0];
    const float* enh   = (const float*)d_in[1];
    const float* noisy = (const float*)d_in[2];
    const float* W1    = (const float*)d_in[3];
    const float* b1    = (const float*)d_in[4];
    const float* a1    = (const float*)d_in[5];
    const float* W2    = (const float*)d_in[6];
    const float* b2    = (const float*)d_in[7];
    const float* a2    = (const float*)d_in[8];
    const float* W3    = (const float*)d_in[9];
    const float* b3    = (const float*)d_in[10];
    float* out = (float*)d_out;

    cudaFuncSetAttribute(mlp_mma_kernel, cudaFuncAttributeMaxDynamicSharedMemorySize, MLP_SMEM);

    mlp_mma_kernel<<<M_ / TOK, 512, MLP_SMEM>>>(gru, W1, b1, a1, W2, b2, a2, W3, b3);
    compress_kernel<<<(B_ * CPB) / 8, 256>>>(enh, noisy, out);
    scale_kernel<<<((B_ * N_ / 4) + 255) / 256, 256>>>(out);
}

// round 7
// speedup vs baseline: 2.3689x; 1.0955x over previous
#include <cuda_runtime.h>
#include <cuda_bf16.h>
#include <math.h>
#include <stdint.h>

// ---------------- problem constants ----------------
#define B_    16
#define T_    4000
#define GRUH  256
#define H1_   128
#define H2_   64
#define N_    320000          // T_ * HOP(80)
#define M_    (B_ * T_)       // 64000 tokens

// ---------------- device scratch ----------------
__device__ float g_ratio[M_];
__device__ int   g_max_out_i;
__device__ int   g_max_enh_i;

// =====================================================================
// helpers
// =====================================================================
__device__ __forceinline__ uint32_t pack_bf16x2(__nv_bfloat16 a, __nv_bfloat16 b) {
    return (uint32_t)__bfloat16_as_ushort(a) | ((uint32_t)__bfloat16_as_ushort(b) << 16);
}
__device__ __forceinline__ void split2(float v0, float v1, uint32_t& hi, uint32_t& lo) {
    __nv_bfloat16 h0 = __float2bfloat16_rn(v0);
    __nv_bfloat16 h1 = __float2bfloat16_rn(v1);
    float l0 = v0 - __bfloat162float(h0);
    float l1 = v1 - __bfloat162float(h1);
    hi = pack_bf16x2(h0, h1);
    lo = pack_bf16x2(__float2bfloat16_rn(l0), __float2bfloat16_rn(l1));
}
// m16n8k16 bf16 MMA, f32 accumulate (portable PTX, sm_80+)
__device__ __forceinline__ void mma_bf16_(float c[4], const uint32_t a[4],
                                          uint32_t b0, uint32_t b1) {
    asm volatile(
        "mma.sync.aligned.m16n8k16.row.col.f32.bf16.bf16.f32 "
        "{%0,%1,%2,%3}, {%4,%5,%6,%7}, {%8,%9}, {%0,%1,%2,%3};"
        : "+f"(c[0]), "+f"(c[1]), "+f"(c[2]), "+f"(c[3])
        : "r"(a[0]), "r"(a[1]), "r"(a[2]), "r"(a[3]), "r"(b0), "r"(b1));
}
#define MMA(c, a, b0, b1) mma_bf16_(c, a, b0, b1)

// =====================================================================
// Kernel A: fused split-bf16 MLP via mma.sync  ->  ratio[m]
//   (unchanged from R6 — 123.4us config)
// =====================================================================
#define TOK 256

#define W1_GSTRIDE 68
#define W2_GSTRIDE 36
#define H1_WSTRIDE 68

#define SO_W2Q  0
#define SO_B1   36864
#define SO_B2   37376
#define SO_W3   37632
#define SO_SC   37888
#define SO_W1Q  38016
#define SO_H1H  38016
#define SO_H1L  107648
#define MLP_SMEM 177280

__global__ __launch_bounds__(512, 1)
void mlp_mma_kernel(const float* __restrict__ X,
                    const float* __restrict__ W1, const float* __restrict__ b1,
                    const float* __restrict__ a1p,
                    const float* __restrict__ W2, const float* __restrict__ b2,
                    const float* __restrict__ a2p,
                    const float* __restrict__ W3, const float* __restrict__ b3)
{
    extern __shared__ char sm[];
    const int tid  = threadIdx.x;
    const int wid  = tid >> 5;
    const int lane = tid & 31;
    const int grp  = lane >> 2;
    const int tig  = lane & 3;
    const int m0   = blockIdx.x * TOK;

    uint4* w1q = (uint4*)(sm + SO_W1Q);
    uint4* w2q = (uint4*)(sm + SO_W2Q);
    uint32_t* h1h = (uint32_t*)(sm + SO_H1H);
    uint32_t* h1l = (uint32_t*)(sm + SO_H1L);
    float* b1s = (float*)(sm + SO_B1);
    float* b2s = (float*)(sm + SO_B2);
    float* w3s = (float*)(sm + SO_W3);
    float* scl = (float*)(sm + SO_SC);

    if (blockIdx.x == 0 && tid == 0) { g_max_out_i = 0; g_max_enh_i = 0; }

    if (tid < 128) b1s[tid] = b1[tid];
    else if (tid < 192) b2s[tid - 128] = b2[tid - 128];
    else if (tid < 256) w3s[tid - 192] = W3[2 * H2_ + (tid - 192)];
    if (tid == 0) { scl[0] = *a1p; scl[1] = *a2p; scl[2] = b3[2]; }

    {
        const int row = tid >> 2;
        const int q   = tid & 3;
        const float* src = W1 + (size_t)row * GRUH;
        #pragma unroll
        for (int kk = 0; kk < 4; ++kk) {
            const int kt = q * 4 + kk;
            const float4* s4 = (const float4*)(src + kt * 16);
            float4 f0 = s4[0], f1 = s4[1], f2 = s4[2], f3 = s4[3];
            uint32_t h[8], l[8];
            split2(f0.x, f0.y, h[0], l[0]); split2(f0.z, f0.w, h[1], l[1]);
            split2(f1.x, f1.y, h[2], l[2]); split2(f1.z, f1.w, h[3], l[3]);
            split2(f2.x, f2.y, h[4], l[4]); split2(f2.z, f2.w, h[5], l[5]);
            split2(f3.x, f3.y, h[6], l[6]); split2(f3.z, f3.w, h[7], l[7]);
            uint4* g = w1q + row * W1_GSTRIDE + kt * 4;
            #pragma unroll
            for (int t = 0; t < 4; ++t)
                g[t] = make_uint4(h[t], h[t + 4], l[t], l[t + 4]);
        }
    }
    {
        const int row = tid >> 3;
        const int kt  = tid & 7;
        const float4* s4 = (const float4*)(W2 + (size_t)row * H1_ + kt * 16);
        float4 f0 = s4[0], f1 = s4[1], f2 = s4[2], f3 = s4[3];
        uint32_t h[8], l[8];
        split2(f0.x, f0.y, h[0], l[0]); split2(f0.z, f0.w, h[1], l[1]);
        split2(f1.x, f1.y, h[2], l[2]); split2(f1.z, f1.w, h[3], l[3]);
        split2(f2.x, f2.y, h[4], l[4]); split2(f2.z, f2.w, h[5], l[5]);
        split2(f3.x, f3.y, h[6], l[6]); split2(f3.z, f3.w, h[7], l[7]);
        uint4* g = w2q + row * W2_GSTRIDE + kt * 4;
        #pragma unroll
        for (int t = 0; t < 4; ++t)
            g[t] = make_uint4(h[t], h[t + 4], l[t], l[t + 4]);
    }
    __syncthreads();

    const int wid_m  = wid >> 1;
    const int nhalf  = wid & 1;
    const float* xr0  = X + (size_t)(m0 + wid_m * 32 + grp) * GRUH;
    const float* xr8  = xr0 + 8  * GRUH;
    const float* xr16 = xr0 + 16 * GRUH;
    const float* xr24 = xr0 + 24 * GRUH;

    float acc[2][8][4];
    #pragma unroll
    for (int t = 0; t < 2; ++t)
        #pragma unroll
        for (int nt = 0; nt < 8; ++nt)
            #pragma unroll
            for (int j = 0; j < 4; ++j) acc[t][nt][j] = 0.0f;

    float2 c00, c10, c20, c30, c01, c11, c21, c31;
    {
        const int k0 = tig * 2;
        c00 = *(const float2*)(xr0  + k0);  c01 = *(const float2*)(xr0  + k0 + 8);
        c10 = *(const float2*)(xr8  + k0);  c11 = *(const float2*)(xr8  + k0 + 8);
        c20 = *(const float2*)(xr16 + k0);  c21 = *(const float2*)(xr16 + k0 + 8);
        c30 = *(const float2*)(xr24 + k0);  c31 = *(const float2*)(xr24 + k0 + 8);
    }

    #pragma unroll 1
    for (int kt = 0; kt < 16; ++kt) {
        uint32_t ah0[4], al0[4], ah1[4], al1[4];
        split2(c00.x, c00.y, ah0[0], al0[0]);
        split2(c10.x, c10.y, ah0[1], al0[1]);
        split2(c01.x, c01.y, ah0[2], al0[2]);
        split2(c11.x, c11.y, ah0[3], al0[3]);
        split2(c20.x, c20.y, ah1[0], al1[0]);
        split2(c30.x, c30.y, ah1[1], al1[1]);
        split2(c21.x, c21.y, ah1[2], al1[2]);
        split2(c31.x, c31.y, ah1[3], al1[3]);

        {
            const int ktn = (kt < 15) ? kt + 1 : 15;
            const int k0 = ktn * 16 + tig * 2;
            c00 = *(const float2*)(xr0  + k0);  c01 = *(const float2*)(xr0  + k0 + 8);
            c10 = *(const float2*)(xr8  + k0);  c11 = *(const float2*)(xr8  + k0 + 8);
            c20 = *(const float2*)(xr16 + k0);  c21 = *(const float2*)(xr16 + k0 + 8);
            c30 = *(const float2*)(xr24 + k0);  c31 = *(const float2*)(xr24 + k0 + 8);
        }

        const uint4* p = w1q + (nhalf * 64 + grp) * W1_GSTRIDE + kt * 4 + tig;
        #pragma unroll
        for (int nt = 0; nt < 8; ++nt) {
            uint4 g = *p;
            p += 8 * W1_GSTRIDE;
            MMA(acc[0][nt], ah0, g.x, g.y);
            MMA(acc[0][nt], ah0, g.z, g.w);
            MMA(acc[0][nt], al0, g.x, g.y);
            MMA(acc[1][nt], ah1, g.x, g.y);
            MMA(acc[1][nt], ah1, g.z, g.w);
            MMA(acc[1][nt], al1, g.x, g.y);
        }
    }
    __syncthreads();

    {
        const float A1 = scl[0];
        const int rbase = wid_m * 32 + grp;
        #pragma unroll
        for (int t = 0; t < 2; ++t) {
            const int r = rbase + t * 16;
            #pragma unroll
            for (int nt = 0; nt < 8; ++nt) {
                const int col0 = nhalf * 64 + nt * 8 + tig * 2;
                float v00 = acc[t][nt][0] + b1s[col0];
                float v01 = acc[t][nt][1] + b1s[col0 + 1];
                float v80 = acc[t][nt][2] + b1s[col0];
                float v81 = acc[t][nt][3] + b1s[col0 + 1];
                v00 = (v00 >= 0.0f) ? v00 : A1 * v00;
                v01 = (v01 >= 0.0f) ? v01 : A1 * v01;
                v80 = (v80 >= 0.0f) ? v80 : A1 * v80;
                v81 = (v81 >= 0.0f) ? v81 : A1 * v81;
                uint32_t h0, l0, h8, l8;
                split2(v00, v01, h0, l0);
                split2(v80, v81, h8, l8);
                const int cw = nhalf * 32 + nt * 4 + tig;
                const int w0 = r * H1_WSTRIDE + cw;
                const int w8 = (r + 8) * H1_WSTRIDE + cw;
                h1h[w0] = h0; h1l[w0] = l0;
                h1h[w8] = h8; h1l[w8] = l8;
            }
        }
    }
    __syncthreads();

    float acc2[8][4];
    #pragma unroll
    for (int nt = 0; nt < 8; ++nt)
        #pragma unroll
        for (int j = 0; j < 4; ++j) acc2[nt][j] = 0.0f;

    const int r0w = (wid * 16 + grp) * H1_WSTRIDE;
    const int r8w = (wid * 16 + grp + 8) * H1_WSTRIDE;

    #pragma unroll 1
    for (int kt = 0; kt < 8; ++kt) {
        const int wbase = kt * 8 + tig;
        uint32_t ah[4], al[4];
        ah[0] = h1h[r0w + wbase];     al[0] = h1l[r0w + wbase];
        ah[1] = h1h[r8w + wbase];     al[1] = h1l[r8w + wbase];
        ah[2] = h1h[r0w + wbase + 4]; al[2] = h1l[r0w + wbase + 4];
        ah[3] = h1h[r8w + wbase + 4]; al[3] = h1l[r8w + wbase + 4];
        const uint4* p = w2q + grp * W2_GSTRIDE + kt * 4 + tig;
        #pragma unroll
        for (int nt = 0; nt < 8; ++nt) {
            uint4 g = *p;
            p += 8 * W2_GSTRIDE;
            MMA(acc2[nt], ah, g.x, g.y);
            MMA(acc2[nt], ah, g.z, g.w);
            MMA(acc2[nt], al, g.x, g.y);
        }
    }

    {
        const float A2 = scl[1];
        float p0 = 0.0f, p8 = 0.0f;
        #pragma unroll
        for (int nt = 0; nt < 8; ++nt) {
            const int col0 = nt * 8 + tig * 2;
            float v00 = acc2[nt][0] + b2s[col0];
            float v01 = acc2[nt][1] + b2s[col0 + 1];
            float v80 = acc2[nt][2] + b2s[col0];
            float v81 = acc2[nt][3] + b2s[col0 + 1];
            v00 = (v00 >= 0.0f) ? v00 : A2 * v00;
            v01 = (v01 >= 0.0f) ? v01 : A2 * v01;
            v80 = (v80 >= 0.0f) ? v80 : A2 * v80;
            v81 = (v81 >= 0.0f) ? v81 : A2 * v81;
            p0 = fmaf(v00, w3s[col0], fmaf(v01, w3s[col0 + 1], p0));
            p8 = fmaf(v80, w3s[col0], fmaf(v81, w3s[col0 + 1], p8));
        }
        p0 += __shfl_xor_sync(0xffffffffu, p0, 1);
        p0 += __shfl_xor_sync(0xffffffffu, p0, 2);
        p8 += __shfl_xor_sync(0xffffffffu, p8, 1);
        p8 += __shfl_xor_sync(0xffffffffu, p8, 2);
        if (tig == 0) {
            const float bb3 = scl[2];
            float pa = p0 + bb3;
            float pb = p8 + bb3;
            float spa = fmaxf(pa, 0.0f) + log1pf(expf(-fabsf(pa)));
            float spb = fmaxf(pb, 0.0f) + log1pf(expf(-fabsf(pb)));
            float ra = fminf(fmaxf(spa + 1.0f, 1.0f), 20.0f);
            float rb = fminf(fmaxf(spb + 1.0f, 1.0f), 20.0f);
            g_ratio[m0 + wid * 16 + grp]     = ra;
            g_ratio[m0 + wid * 16 + grp + 8] = rb;
        }
    }
}

// =====================================================================
// Kernel B v2: blocked IIR — 8 samples/lane sequential + one warp scan
// per 256-sample window (8x fewer shuffles than v1). Exact algebra:
//   s_j = loc_j + 0.9^{j+1} * carry_into_lane
//   carry_into_lane i = I_{i-1} + q^i * s_in,  q = 0.9^8
//   I = warp inclusive scan of per-lane final locals with hop weight q.
// =====================================================================
#define CCHUNK 2560
#define CWARM  256
#define C_PB   (N_ / CCHUNK)    // 125 chunks per batch

__device__ __forceinline__ float interp_ratio(const float* __restrict__ rb, int n)
{
    float src = ((float)n + 0.5f) * 0.0125f - 0.5f;
    src = fminf(fmaxf(src, 0.0f), 3999.0f);
    float f0 = floorf(src);
    int   i0 = (int)f0;
    int   i1 = min(i0 + 1, 3999);
    float w  = src - f0;
    return rb[i0] * (1.0f - w) + rb[i1] * w;
}
__device__ __forceinline__ float gain_of(float x, float thr, float ratio)
{
    float env = fabsf(x);
    float gr  = (env > thr) ? (thr + (env - thr) / ratio) : env;
    float g   = gr / (env + 1e-8f);
    return fminf(fmaxf(g, 0.1f), 2.0f);
}

__global__ __launch_bounds__(256)
void compress_kernel(const float* __restrict__ enh,
                     const float* __restrict__ noisy,
                     float* __restrict__ out)
{
    const int w    = (blockIdx.x * blockDim.x + threadIdx.x) >> 5;
    const int lane = threadIdx.x & 31;
    const int b     = w / C_PB;
    const int chunk = w % C_PB;
    const int t0    = chunk * CCHUNK;
    const int start = (chunk == 0) ? 0 : (t0 - CWARM);

    const float* eb = enh   + (size_t)b * N_;
    const float* nb = noisy + (size_t)b * N_;
    float*       ob = out   + (size_t)b * N_;
    const float* rb = g_ratio + b * T_;

    const float q   = 0.43046721f;                    // 0.9^8
    const float qi  = powf(q, (float)lane);           // q^lane
    const float q32 = 1.9342813113834067e-12f;        // q^32 = 0.9^256

    // init carries: s = gain at first sample of window
    float s_in_e, s_in_r;
    {
        float e  = eb[start];
        float nn = nb[start];
        float ratio = interp_ratio(rb, start);
        s_in_e = gain_of(e, 0.3f, ratio);
        s_in_r = gain_of(nn - e, 0.1f, ratio * 0.5f);
    }

    float mx_out = 0.0f, mx_enh = 0.0f;
    const int nend = t0 + CCHUNK;

    #pragma unroll 1
    for (int g0 = start; g0 < nend; g0 += 256) {
        const int n0 = g0 + lane * 8;
        float4 e0 = *(const float4*)(eb + n0);
        float4 e1 = *(const float4*)(eb + n0 + 4);
        float4 x0 = *(const float4*)(nb + n0);
        float4 x1 = *(const float4*)(nb + n0 + 4);
        float e[8] = {e0.x, e0.y, e0.z, e0.w, e1.x, e1.y, e1.z, e1.w};
        float x[8] = {x0.x, x0.y, x0.z, x0.w, x1.x, x1.y, x1.z, x1.w};

        float r[8], le[8], lr[8];
        float se = 0.0f, sr = 0.0f;
        #pragma unroll
        for (int j = 0; j < 8; ++j) {
            r[j] = x[j] - e[j];
            float ratio = interp_ratio(rb, n0 + j);
            float ge = gain_of(e[j], 0.3f, ratio);
            float gr = gain_of(r[j], 0.1f, ratio * 0.5f);
            se = fmaf(0.9f, se, 0.1f * ge);  le[j] = se;
            sr = fmaf(0.9f, sr, 0.1f * gr);  lr[j] = sr;
        }

        // warp inclusive scan over per-lane finals (hop weight q^{1,2,4,8,16})
        float Ie = se, Ir = sr, t;
        t = __shfl_up_sync(0xffffffffu, Ie, 1);  if (lane >= 1)  Ie = fmaf(0.43046721f,            t, Ie);
        t = __shfl_up_sync(0xffffffffu, Ir, 1);  if (lane >= 1)  Ir = fmaf(0.43046721f,            t, Ir);
        t = __shfl_up_sync(0xffffffffu, Ie, 2);  if (lane >= 2)  Ie = fmaf(0.1853020188851841f,    t, Ie);
        t = __shfl_up_sync(0xffffffffu, Ir, 2);  if (lane >= 2)  Ir = fmaf(0.1853020188851841f,    t, Ir);
        t = __shfl_up_sync(0xffffffffu, Ie, 4);  if (lane >= 4)  Ie = fmaf(0.03433683820292512f,   t, Ie);
        t = __shfl_up_sync(0xffffffffu, Ir, 4);  if (lane >= 4)  Ir = fmaf(0.03433683820292512f,   t, Ir);
        t = __shfl_up_sync(0xffffffffu, Ie, 8);  if (lane >= 8)  Ie = fmaf(0.001179018457773862f,  t, Ie);
        t = __shfl_up_sync(0xffffffffu, Ir, 8);  if (lane >= 8)  Ir = fmaf(0.001179018457773862f,  t, Ir);
        t = __shfl_up_sync(0xffffffffu, Ie, 16); if (lane >= 16) Ie = fmaf(1.390084523771456e-06f, t, Ie);
        t = __shfl_up_sync(0xffffffffu, Ir, 16); if (lane >= 16) Ir = fmaf(1.390084523771456e-06f, t, Ir);

        // carry into this lane
        float ce = __shfl_up_sync(0xffffffffu, Ie, 1); if (lane == 0) ce = 0.0f;
        float cr = __shfl_up_sync(0xffffffffu, Ir, 1); if (lane == 0) cr = 0.0f;
        ce = fmaf(qi, s_in_e, ce);
        cr = fmaf(qi, s_in_r, cr);

        // next window's incoming carry
        float Ie31 = __shfl_sync(0xffffffffu, Ie, 31);
        float Ir31 = __shfl_sync(0xffffffffu, Ir, 31);
        s_in_e = fmaf(q32, s_in_e, Ie31);
        s_in_r = fmaf(q32, s_in_r, Ir31);

        if (g0 >= t0) {
            const float d[8] = {0.9f, 0.81f, 0.729f, 0.6561f,
                                0.59049f, 0.531441f, 0.4782969f, 0.43046721f};
            float o[8];
            #pragma unroll
            for (int j = 0; j < 8; ++j) {
                float sej = fmaf(d[j], ce, le[j]);
                float srj = fmaf(d[j], cr, lr[j]);
                o[j] = fmaf(sej, e[j], 0.1f * (srj * r[j]));
                mx_out = fmaxf(mx_out, fabsf(o[j]));
                mx_enh = fmaxf(mx_enh, fabsf(e[j]));
            }
            *(float4*)(ob + n0)     = make_float4(o[0], o[1], o[2], o[3]);
            *(float4*)(ob + n0 + 4) = make_float4(o[4], o[5], o[6], o[7]);
        }
    }

    #pragma unroll
    for (int off = 16; off > 0; off >>= 1) {
        mx_out = fmaxf(mx_out, __shfl_xor_sync(0xffffffffu, mx_out, off));
        mx_enh = fmaxf(mx_enh, __shfl_xor_sync(0xffffffffu, mx_enh, off));
    }
    if (lane == 0) {
        atomicMax(&g_max_out_i, __float_as_int(mx_out));
        atomicMax(&g_max_enh_i, __float_as_int(mx_enh));
    }
}

// =====================================================================
// Kernel C: normalize
// =====================================================================
__global__ __launch_bounds__(256)
void scale_kernel(float* __restrict__ out)
{
    const float mo = __int_as_float(g_max_out_i);
    const float me = __int_as_float(g_max_enh_i);
    const float s  = me / (mo + 1e-8f);
    const int i = blockIdx.x * blockDim.x + threadIdx.x;
    const int n4 = (B_ * N_) / 4;
    if (i < n4) {
        float4* o4 = (float4*)out;
        float4 v = o4[i];
        v.x *= s; v.y *= s; v.z *= s; v.w *= s;
        o4[i] = v;
    }
}

// =====================================================================
extern "C" void kernel_launch(void* const* d_in, const int* in_sizes, int n_in,
                              void* d_out, int out_size)
{
    const float* gru   = (const float*)d_in[0];
    const float* enh   = (const float*)d_in[1];
    const float* noisy = (const float*)d_in[2];
    const float* W1    = (const float*)d_in[3];
    const float* b1    = (const float*)d_in[4];
    const float* a1    = (const float*)d_in[5];
    const float* W2    = (const float*)d_in[6];
    const float* b2    = (const float*)d_in[7];
    const float* a2    = (const float*)d_in[8];
    const float* W3    = (const float*)d_in[9];
    const float* b3    = (const float*)d_in[10];
    float* out = (float*)d_out;

    cudaFuncSetAttribute(mlp_mma_kernel, cudaFuncAttributeMaxDynamicSharedMemorySize, MLP_SMEM);

    mlp_mma_kernel<<<M_ / TOK, 512, MLP_SMEM>>>(gru, W1, b1, a1, W2, b2, a2, W3, b3);
    compress_kernel<<<(B_ * C_PB) / 8, 256>>>(enh, noisy, out);   // 2000 warps
    scale_kernel<<<((B_ * N_ / 4) + 255) / 256, 256>>>(out);
}

// round 8
// speedup vs baseline: 2.7197x; 1.1481x over previous
#include <cuda_runtime.h>
#include <cuda_bf16.h>
#include <math.h>
#include <stdint.h>

// ---------------- problem constants ----------------
#define B_    16
#define T_    4000
#define GRUH  256
#define H1_   128
#define H2_   64
#define N_    320000          // T_ * HOP(80)
#define M_    (B_ * T_)       // 64000 tokens

// ---------------- device scratch ----------------
__device__ float g_ratio[M_];
__device__ int   g_max_out_i;
__device__ int   g_max_enh_i;

// =====================================================================
// helpers
// =====================================================================
__device__ __forceinline__ uint32_t pack_bf16x2(__nv_bfloat16 a, __nv_bfloat16 b) {
    return (uint32_t)__bfloat16_as_ushort(a) | ((uint32_t)__bfloat16_as_ushort(b) << 16);
}
__device__ __forceinline__ void split2(float v0, float v1, uint32_t& hi, uint32_t& lo) {
    __nv_bfloat16 h0 = __float2bfloat16_rn(v0);
    __nv_bfloat16 h1 = __float2bfloat16_rn(v1);
    float l0 = v0 - __bfloat162float(h0);
    float l1 = v1 - __bfloat162float(h1);
    hi = pack_bf16x2(h0, h1);
    lo = pack_bf16x2(__float2bfloat16_rn(l0), __float2bfloat16_rn(l1));
}
// m16n8k16 bf16 MMA, f32 accumulate (portable PTX, sm_80+)
__device__ __forceinline__ void mma_bf16_(float c[4], const uint32_t a[4],
                                          uint32_t b0, uint32_t b1) {
    asm volatile(
        "mma.sync.aligned.m16n8k16.row.col.f32.bf16.bf16.f32 "
        "{%0,%1,%2,%3}, {%4,%5,%6,%7}, {%8,%9}, {%0,%1,%2,%3};"
        : "+f"(c[0]), "+f"(c[1]), "+f"(c[2]), "+f"(c[3])
        : "r"(a[0]), "r"(a[1]), "r"(a[2]), "r"(a[3]), "r"(b0), "r"(b1));
}
#define MMA(c, a, b0, b1) mma_bf16_(c, a, b0, b1)

// =====================================================================
// Kernel A: fused split-bf16 MLP via mma.sync  ->  ratio[m]
//   256 tokens/CTA, 250 CTAs, 512 threads; depth-1 granule prefetch.
// =====================================================================
#define TOK 256

#define W1_GSTRIDE 68
#define W2_GSTRIDE 36
#define H1_WSTRIDE 68

#define SO_W2Q  0
#define SO_B1   36864
#define SO_B2   37376
#define SO_W3   37632
#define SO_SC   37888
#define SO_W1Q  38016
#define SO_H1H  38016
#define SO_H1L  107648
#define MLP_SMEM 177280

__global__ __launch_bounds__(512, 1)
void mlp_mma_kernel(const float* __restrict__ X,
                    const float* __restrict__ W1, const float* __restrict__ b1,
                    const float* __restrict__ a1p,
                    const float* __restrict__ W2, const float* __restrict__ b2,
                    const float* __restrict__ a2p,
                    const float* __restrict__ W3, const float* __restrict__ b3)
{
    extern __shared__ char sm[];
    const int tid  = threadIdx.x;
    const int wid  = tid >> 5;
    const int lane = tid & 31;
    const int grp  = lane >> 2;
    const int tig  = lane & 3;
    const int m0   = blockIdx.x * TOK;

    uint4* w1q = (uint4*)(sm + SO_W1Q);
    uint4* w2q = (uint4*)(sm + SO_W2Q);
    uint32_t* h1h = (uint32_t*)(sm + SO_H1H);
    uint32_t* h1l = (uint32_t*)(sm + SO_H1L);
    float* b1s = (float*)(sm + SO_B1);
    float* b2s = (float*)(sm + SO_B2);
    float* w3s = (float*)(sm + SO_W3);
    float* scl = (float*)(sm + SO_SC);

    if (blockIdx.x == 0 && tid == 0) { g_max_out_i = 0; g_max_enh_i = 0; }

    if (tid < 128) b1s[tid] = b1[tid];
    else if (tid < 192) b2s[tid - 128] = b2[tid - 128];
    else if (tid < 256) w3s[tid - 192] = W3[2 * H2_ + (tid - 192)];
    if (tid == 0) { scl[0] = *a1p; scl[1] = *a2p; scl[2] = b3[2]; }

    {
        const int row = tid >> 2;
        const int q   = tid & 3;
        const float* src = W1 + (size_t)row * GRUH;
        #pragma unroll
        for (int kk = 0; kk < 4; ++kk) {
            const int kt = q * 4 + kk;
            const float4* s4 = (const float4*)(src + kt * 16);
            float4 f0 = s4[0], f1 = s4[1], f2 = s4[2], f3 = s4[3];
            uint32_t h[8], l[8];
            split2(f0.x, f0.y, h[0], l[0]); split2(f0.z, f0.w, h[1], l[1]);
            split2(f1.x, f1.y, h[2], l[2]); split2(f1.z, f1.w, h[3], l[3]);
            split2(f2.x, f2.y, h[4], l[4]); split2(f2.z, f2.w, h[5], l[5]);
            split2(f3.x, f3.y, h[6], l[6]); split2(f3.z, f3.w, h[7], l[7]);
            uint4* g = w1q + row * W1_GSTRIDE + kt * 4;
            #pragma unroll
            for (int t = 0; t < 4; ++t)
                g[t] = make_uint4(h[t], h[t + 4], l[t], l[t + 4]);
        }
    }
    {
        const int row = tid >> 3;
        const int kt  = tid & 7;
        const float4* s4 = (const float4*)(W2 + (size_t)row * H1_ + kt * 16);
        float4 f0 = s4[0], f1 = s4[1], f2 = s4[2], f3 = s4[3];
        uint32_t h[8], l[8];
        split2(f0.x, f0.y, h[0], l[0]); split2(f0.z, f0.w, h[1], l[1]);
        split2(f1.x, f1.y, h[2], l[2]); split2(f1.z, f1.w, h[3], l[3]);
        split2(f2.x, f2.y, h[4], l[4]); split2(f2.z, f2.w, h[5], l[5]);
        split2(f3.x, f3.y, h[6], l[6]); split2(f3.z, f3.w, h[7], l[7]);
        uint4* g = w2q + row * W2_GSTRIDE + kt * 4;
        #pragma unroll
        for (int t = 0; t < 4; ++t)
            g[t] = make_uint4(h[t], h[t + 4], l[t], l[t + 4]);
    }
    __syncthreads();

    const int wid_m  = wid >> 1;
    const int nhalf  = wid & 1;
    const float* xr0  = X + (size_t)(m0 + wid_m * 32 + grp) * GRUH;
    const float* xr8  = xr0 + 8  * GRUH;
    const float* xr16 = xr0 + 16 * GRUH;
    const float* xr24 = xr0 + 24 * GRUH;

    float acc[2][8][4];
    #pragma unroll
    for (int t = 0; t < 2; ++t)
        #pragma unroll
        for (int nt = 0; nt < 8; ++nt)
            #pragma unroll
            for (int j = 0; j < 4; ++j) acc[t][nt][j] = 0.0f;

    float2 c00, c10, c20, c30, c01, c11, c21, c31;
    {
        const int k0 = tig * 2;
        c00 = *(const float2*)(xr0  + k0);  c01 = *(const float2*)(xr0  + k0 + 8);
        c10 = *(const float2*)(xr8  + k0);  c11 = *(const float2*)(xr8  + k0 + 8);
        c20 = *(const float2*)(xr16 + k0);  c21 = *(const float2*)(xr16 + k0 + 8);
        c30 = *(const float2*)(xr24 + k0);  c31 = *(const float2*)(xr24 + k0 + 8);
    }

    #pragma unroll 1
    for (int kt = 0; kt < 16; ++kt) {
        uint32_t ah0[4], al0[4], ah1[4], al1[4];
        split2(c00.x, c00.y, ah0[0], al0[0]);
        split2(c10.x, c10.y, ah0[1], al0[1]);
        split2(c01.x, c01.y, ah0[2], al0[2]);
        split2(c11.x, c11.y, ah0[3], al0[3]);
        split2(c20.x, c20.y, ah1[0], al1[0]);
        split2(c30.x, c30.y, ah1[1], al1[1]);
        split2(c21.x, c21.y, ah1[2], al1[2]);
        split2(c31.x, c31.y, ah1[3], al1[3]);

        {
            const int ktn = (kt < 15) ? kt + 1 : 15;
            const int k0 = ktn * 16 + tig * 2;
            c00 = *(const float2*)(xr0  + k0);  c01 = *(const float2*)(xr0  + k0 + 8);
            c10 = *(const float2*)(xr8  + k0);  c11 = *(const float2*)(xr8  + k0 + 8);
            c20 = *(const float2*)(xr16 + k0);  c21 = *(const float2*)(xr16 + k0 + 8);
            c30 = *(const float2*)(xr24 + k0);  c31 = *(const float2*)(xr24 + k0 + 8);
        }

        const uint4* base = w1q + (nhalf * 64 + grp) * W1_GSTRIDE + kt * 4 + tig;
        uint4 g = base[0];
        #pragma unroll
        for (int nt = 0; nt < 8; ++nt) {
            // prefetch next granule before consuming current one
            uint4 gn = base[((nt < 7) ? nt + 1 : 7) * 8 * W1_GSTRIDE];
            MMA(acc[0][nt], ah0, g.x, g.y);
            MMA(acc[0][nt], ah0, g.z, g.w);
            MMA(acc[0][nt], al0, g.x, g.y);
            MMA(acc[1][nt], ah1, g.x, g.y);
            MMA(acc[1][nt], ah1, g.z, g.w);
            MMA(acc[1][nt], al1, g.x, g.y);
            g = gn;
        }
    }
    __syncthreads();

    {
        const float A1 = scl[0];
        const int rbase = wid_m * 32 + grp;
        #pragma unroll
        for (int t = 0; t < 2; ++t) {
            const int r = rbase + t * 16;
            #pragma unroll
            for (int nt = 0; nt < 8; ++nt) {
                const int col0 = nhalf * 64 + nt * 8 + tig * 2;
                float v00 = acc[t][nt][0] + b1s[col0];
                float v01 = acc[t][nt][1] + b1s[col0 + 1];
                float v80 = acc[t][nt][2] + b1s[col0];
                float v81 = acc[t][nt][3] + b1s[col0 + 1];
                v00 = (v00 >= 0.0f) ? v00 : A1 * v00;
                v01 = (v01 >= 0.0f) ? v01 : A1 * v01;
                v80 = (v80 >= 0.0f) ? v80 : A1 * v80;
                v81 = (v81 >= 0.0f) ? v81 : A1 * v81;
                uint32_t h0, l0, h8, l8;
                split2(v00, v01, h0, l0);
                split2(v80, v81, h8, l8);
                const int cw = nhalf * 32 + nt * 4 + tig;
                const int w0 = r * H1_WSTRIDE + cw;
                const int w8 = (r + 8) * H1_WSTRIDE + cw;
                h1h[w0] = h0; h1l[w0] = l0;
                h1h[w8] = h8; h1l[w8] = l8;
            }
        }
    }
    __syncthreads();

    float acc2[8][4];
    #pragma unroll
    for (int nt = 0; nt < 8; ++nt)
        #pragma unroll
        for (int j = 0; j < 4; ++j) acc2[nt][j] = 0.0f;

    const int r0w = (wid * 16 + grp) * H1_WSTRIDE;
    const int r8w = (wid * 16 + grp + 8) * H1_WSTRIDE;

    #pragma unroll 1
    for (int kt = 0; kt < 8; ++kt) {
        const int wbase = kt * 8 + tig;
        uint32_t ah[4], al[4];
        ah[0] = h1h[r0w + wbase];     al[0] = h1l[r0w + wbase];
        ah[1] = h1h[r8w + wbase];     al[1] = h1l[r8w + wbase];
        ah[2] = h1h[r0w + wbase + 4]; al[2] = h1l[r0w + wbase + 4];
        ah[3] = h1h[r8w + wbase + 4]; al[3] = h1l[r8w + wbase + 4];
        const uint4* base = w2q + grp * W2_GSTRIDE + kt * 4 + tig;
        uint4 g = base[0];
        #pragma unroll
        for (int nt = 0; nt < 8; ++nt) {
            uint4 gn = base[((nt < 7) ? nt + 1 : 7) * 8 * W2_GSTRIDE];
            MMA(acc2[nt], ah, g.x, g.y);
            MMA(acc2[nt], ah, g.z, g.w);
            MMA(acc2[nt], al, g.x, g.y);
            g = gn;
        }
    }

    {
        const float A2 = scl[1];
        float p0 = 0.0f, p8 = 0.0f;
        #pragma unroll
        for (int nt = 0; nt < 8; ++nt) {
            const int col0 = nt * 8 + tig * 2;
            float v00 = acc2[nt][0] + b2s[col0];
            float v01 = acc2[nt][1] + b2s[col0 + 1];
            float v80 = acc2[nt][2] + b2s[col0];
            float v81 = acc2[nt][3] + b2s[col0 + 1];
            v00 = (v00 >= 0.0f) ? v00 : A2 * v00;
            v01 = (v01 >= 0.0f) ? v01 : A2 * v01;
            v80 = (v80 >= 0.0f) ? v80 : A2 * v80;
            v81 = (v81 >= 0.0f) ? v81 : A2 * v81;
            p0 = fmaf(v00, w3s[col0], fmaf(v01, w3s[col0 + 1], p0));
            p8 = fmaf(v80, w3s[col0], fmaf(v81, w3s[col0 + 1], p8));
        }
        p0 += __shfl_xor_sync(0xffffffffu, p0, 1);
        p0 += __shfl_xor_sync(0xffffffffu, p0, 2);
        p8 += __shfl_xor_sync(0xffffffffu, p8, 1);
        p8 += __shfl_xor_sync(0xffffffffu, p8, 2);
        if (tig == 0) {
            const float bb3 = scl[2];
            float pa = p0 + bb3;
            float pb = p8 + bb3;
            float spa = fmaxf(pa, 0.0f) + log1pf(expf(-fabsf(pa)));
            float spb = fmaxf(pb, 0.0f) + log1pf(expf(-fabsf(pb)));
            float ra = fminf(fmaxf(spa + 1.0f, 1.0f), 20.0f);
            float rb = fminf(fmaxf(spb + 1.0f, 1.0f), 20.0f);
            g_ratio[m0 + wid * 16 + grp]     = ra;
            g_ratio[m0 + wid * 16 + grp + 8] = rb;
        }
    }
}

// =====================================================================
// Kernel B: blocked IIR (8 samples/lane + warp scan per 256 samples)
//   CCHUNK 1280 -> 500 CTAs (3.4 waves); fast divides via __fdividef.
// =====================================================================
#define CCHUNK 1280
#define CWARM  256
#define C_PB   (N_ / CCHUNK)    // 250 chunks per batch

__device__ __forceinline__ float interp_ratio(const float* __restrict__ rb, int n)
{
    float src = ((float)n + 0.5f) * 0.0125f - 0.5f;
    src = fminf(fmaxf(src, 0.0f), 3999.0f);
    float f0 = floorf(src);
    int   i0 = (int)f0;
    int   i1 = min(i0 + 1, 3999);
    float w  = src - f0;
    return rb[i0] * (1.0f - w) + rb[i1] * w;
}
__device__ __forceinline__ float gain_of(float x, float thr, float ratio)
{
    float env = fabsf(x);
    float gr  = (env > thr) ? (thr + __fdividef(env - thr, ratio)) : env;
    float g   = __fdividef(gr, env + 1e-8f);
    return fminf(fmaxf(g, 0.1f), 2.0f);
}

__global__ __launch_bounds__(256)
void compress_kernel(const float* __restrict__ enh,
                     const float* __restrict__ noisy,
                     float* __restrict__ out)
{
    const int w    = (blockIdx.x * blockDim.x + threadIdx.x) >> 5;
    const int lane = threadIdx.x & 31;
    const int b     = w / C_PB;
    const int chunk = w % C_PB;
    const int t0    = chunk * CCHUNK;
    const int start = (chunk == 0) ? 0 : (t0 - CWARM);

    const float* eb = enh   + (size_t)b * N_;
    const float* nb = noisy + (size_t)b * N_;
    float*       ob = out   + (size_t)b * N_;
    const float* rb = g_ratio + b * T_;

    const float q   = 0.43046721f;                    // 0.9^8
    const float qi  = powf(q, (float)lane);           // q^lane
    const float q32 = 1.9342813113834067e-12f;        // 0.9^256

    float s_in_e, s_in_r;
    {
        float e  = eb[start];
        float nn = nb[start];
        float ratio = interp_ratio(rb, start);
        s_in_e = gain_of(e, 0.3f, ratio);
        s_in_r = gain_of(nn - e, 0.1f, ratio * 0.5f);
    }

    float mx_out = 0.0f, mx_enh = 0.0f;
    const int nend = t0 + CCHUNK;

    #pragma unroll 1
    for (int g0 = start; g0 < nend; g0 += 256) {
        const int n0 = g0 + lane * 8;
        float4 e0 = *(const float4*)(eb + n0);
        float4 e1 = *(const float4*)(eb + n0 + 4);
        float4 x0 = *(const float4*)(nb + n0);
        float4 x1 = *(const float4*)(nb + n0 + 4);
        float e[8] = {e0.x, e0.y, e0.z, e0.w, e1.x, e1.y, e1.z, e1.w};
        float x[8] = {x0.x, x0.y, x0.z, x0.w, x1.x, x1.y, x1.z, x1.w};

        float r[8], le[8], lr[8];
        float se = 0.0f, sr = 0.0f;
        #pragma unroll
        for (int j = 0; j < 8; ++j) {
            r[j] = x[j] - e[j];
            float ratio = interp_ratio(rb, n0 + j);
            float ge = gain_of(e[j], 0.3f, ratio);
            float gr = gain_of(r[j], 0.1f, ratio * 0.5f);
            se = fmaf(0.9f, se, 0.1f * ge);  le[j] = se;
            sr = fmaf(0.9f, sr, 0.1f * gr);  lr[j] = sr;
        }

        float Ie = se, Ir = sr, t;
        t = __shfl_up_sync(0xffffffffu, Ie, 1);  if (lane >= 1)  Ie = fmaf(0.43046721f,            t, Ie);
        t = __shfl_up_sync(0xffffffffu, Ir, 1);  if (lane >= 1)  Ir = fmaf(0.43046721f,            t, Ir);
        t = __shfl_up_sync(0xffffffffu, Ie, 2);  if (lane >= 2)  Ie = fmaf(0.1853020188851841f,    t, Ie);
        t = __shfl_up_sync(0xffffffffu, Ir, 2);  if (lane >= 2)  Ir = fmaf(0.1853020188851841f,    t, Ir);
        t = __shfl_up_sync(0xffffffffu, Ie, 4);  if (lane >= 4)  Ie = fmaf(0.03433683820292512f,   t, Ie);
        t = __shfl_up_sync(0xffffffffu, Ir, 4);  if (lane >= 4)  Ir = fmaf(0.03433683820292512f,   t, Ir);
        t = __shfl_up_sync(0xffffffffu, Ie, 8);  if (lane >= 8)  Ie = fmaf(0.001179018457773862f,  t, Ie);
        t = __shfl_up_sync(0xffffffffu, Ir, 8);  if (lane >= 8)  Ir = fmaf(0.001179018457773862f,  t, Ir);
        t = __shfl_up_sync(0xffffffffu, Ie, 16); if (lane >= 16) Ie = fmaf(1.390084523771456e-06f, t, Ie);
        t = __shfl_up_sync(0xffffffffu, Ir, 16); if (lane >= 16) Ir = fmaf(1.390084523771456e-06f, t, Ir);

        float ce = __shfl_up_sync(0xffffffffu, Ie, 1); if (lane == 0) ce = 0.0f;
        float cr = __shfl_up_sync(0xffffffffu, Ir, 1); if (lane == 0) cr = 0.0f;
        ce = fmaf(qi, s_in_e, ce);
        cr = fmaf(qi, s_in_r, cr);

        float Ie31 = __shfl_sync(0xffffffffu, Ie, 31);
        float Ir31 = __shfl_sync(0xffffffffu, Ir, 31);
        s_in_e = fmaf(q32, s_in_e, Ie31);
        s_in_r = fmaf(q32, s_in_r, Ir31);

        if (g0 >= t0) {
            const float d[8] = {0.9f, 0.81f, 0.729f, 0.6561f,
                                0.59049f, 0.531441f, 0.4782969f, 0.43046721f};
            float o[8];
            #pragma unroll
            for (int j = 0; j < 8; ++j) {
                float sej = fmaf(d[j], ce, le[j]);
                float srj = fmaf(d[j], cr, lr[j]);
                o[j] = fmaf(sej, e[j], 0.1f * (srj * r[j]));
                mx_out = fmaxf(mx_out, fabsf(o[j]));
                mx_enh = fmaxf(mx_enh, fabsf(e[j]));
            }
            *(float4*)(ob + n0)     = make_float4(o[0], o[1], o[2], o[3]);
            *(float4*)(ob + n0 + 4) = make_float4(o[4], o[5], o[6], o[7]);
        }
    }

    #pragma unroll
    for (int off = 16; off > 0; off >>= 1) {
        mx_out = fmaxf(mx_out, __shfl_xor_sync(0xffffffffu, mx_out, off));
        mx_enh = fmaxf(mx_enh, __shfl_xor_sync(0xffffffffu, mx_enh, off));
    }
    if (lane == 0) {
        atomicMax(&g_max_out_i, __float_as_int(mx_out));
        atomicMax(&g_max_enh_i, __float_as_int(mx_enh));
    }
}

// =====================================================================
// Kernel C: normalize
// =====================================================================
__global__ __launch_bounds__(256)
void scale_kernel(float* __restrict__ out)
{
    const float mo = __int_as_float(g_max_out_i);
    const float me = __int_as_float(g_max_enh_i);
    const float s  = me / (mo + 1e-8f);
    const int i = blockIdx.x * blockDim.x + threadIdx.x;
    const int n4 = (B_ * N_) / 4;
    if (i < n4) {
        float4* o4 = (float4*)out;
        float4 v = o4[i];
        v.x *= s; v.y *= s; v.z *= s; v.w *= s;
        o4[i] = v;
    }
}

// =====================================================================
extern "C" void kernel_launch(void* const* d_in, const int* in_sizes, int n_in,
                              void* d_out, int out_size)
{
    const float* gru   = (const float*)d_in[0];
    const float* enh   = (const float*)d_in[1];
    const float* noisy = (const float*)d_in[2];
    const float* W1    = (const float*)d_in[3];
    const float* b1    = (const float*)d_in[4];
    const float* a1    = (const float*)d_in[5];
    const float* W2    = (const float*)d_in[6];
    const float* b2    = (const float*)d_in[7];
    const float* a2    = (const float*)d_in[8];
    const float* W3    = (const float*)d_in[9];
    const float* b3    = (const float*)d_in[10];
    float* out = (float*)d_out;

    cudaFuncSetAttribute(mlp_mma_kernel, cudaFuncAttributeMaxDynamicSharedMemorySize, MLP_SMEM);

    mlp_mma_kernel<<<M_ / TOK, 512, MLP_SMEM>>>(gru, W1, b1, a1, W2, b2, a2, W3, b3);
    compress_kernel<<<(B_ * C_PB) / 8, 256>>>(enh, noisy, out);   // 4000 warps
    scale_kernel<<<((B_ * N_ / 4) + 255) / 256, 256>>>(out);
}

// round 9
// speedup vs baseline: 2.7439x; 1.0089x over previous
#include <cuda_runtime.h>
#include <cuda_bf16.h>
#include <math.h>
#include <stdint.h>

// ---------------- problem constants ----------------
#define B_    16
#define T_    4000
#define GRUH  256
#define H1_   128
#define H2_   64
#define N_    320000          // T_ * HOP(80)
#define M_    (B_ * T_)       // 64000 tokens

// ---------------- device scratch ----------------
__device__ float g_ratio[M_];
__device__ int   g_max_out_i;
__device__ int   g_max_enh_i;

// =====================================================================
// helpers
// =====================================================================
__device__ __forceinline__ uint32_t pack_bf16x2(__nv_bfloat16 a, __nv_bfloat16 b) {
    return (uint32_t)__bfloat16_as_ushort(a) | ((uint32_t)__bfloat16_as_ushort(b) << 16);
}
__device__ __forceinline__ void split2(float v0, float v1, uint32_t& hi, uint32_t& lo) {
    __nv_bfloat16 h0 = __float2bfloat16_rn(v0);
    __nv_bfloat16 h1 = __float2bfloat16_rn(v1);
    float l0 = v0 - __bfloat162float(h0);
    float l1 = v1 - __bfloat162float(h1);
    hi = pack_bf16x2(h0, h1);
    lo = pack_bf16x2(__float2bfloat16_rn(l0), __float2bfloat16_rn(l1));
}
// m16n8k16 bf16 MMA, f32 accumulate (portable PTX, sm_80+)
__device__ __forceinline__ void mma_bf16_(float c[4], const uint32_t a[4],
                                          uint32_t b0, uint32_t b1) {
    asm volatile(
        "mma.sync.aligned.m16n8k16.row.col.f32.bf16.bf16.f32 "
        "{%0,%1,%2,%3}, {%4,%5,%6,%7}, {%8,%9}, {%0,%1,%2,%3};"
        : "+f"(c[0]), "+f"(c[1]), "+f"(c[2]), "+f"(c[3])
        : "r"(a[0]), "r"(a[1]), "r"(a[2]), "r"(a[3]), "r"(b0), "r"(b1));
}
#define MMA(c, a, b0, b1) mma_bf16_(c, a, b0, b1)

// =====================================================================
// Kernel A: fused split-bf16 MLP via mma.sync  ->  ratio[m]
//   256 tokens/CTA, 250 CTAs, 512 threads; depth-1 granule prefetch.
// =====================================================================
#define TOK 256

#define W1_GSTRIDE 68
#define W2_GSTRIDE 36
#define H1_WSTRIDE 68

#define SO_W2Q  0
#define SO_B1   36864
#define SO_B2   37376
#define SO_W3   37632
#define SO_SC   37888
#define SO_W1Q  38016
#define SO_H1H  38016
#define SO_H1L  107648
#define MLP_SMEM 177280

__global__ __launch_bounds__(512, 1)
void mlp_mma_kernel(const float* __restrict__ X,
                    const float* __restrict__ W1, const float* __restrict__ b1,
                    const float* __restrict__ a1p,
                    const float* __restrict__ W2, const float* __restrict__ b2,
                    const float* __restrict__ a2p,
                    const float* __restrict__ W3, const float* __restrict__ b3)
{
    extern __shared__ char sm[];
    const int tid  = threadIdx.x;
    const int wid  = tid >> 5;
    const int lane = tid & 31;
    const int grp  = lane >> 2;
    const int tig  = lane & 3;
    const int m0   = blockIdx.x * TOK;

    uint4* w1q = (uint4*)(sm + SO_W1Q);
    uint4* w2q = (uint4*)(sm + SO_W2Q);
    uint32_t* h1h = (uint32_t*)(sm + SO_H1H);
    uint32_t* h1l = (uint32_t*)(sm + SO_H1L);
    float* b1s = (float*)(sm + SO_B1);
    float* b2s = (float*)(sm + SO_B2);
    float* w3s = (float*)(sm + SO_W3);
    float* scl = (float*)(sm + SO_SC);

    if (blockIdx.x == 0 && tid == 0) { g_max_out_i = 0; g_max_enh_i = 0; }

    if (tid < 128) b1s[tid] = b1[tid];
    else if (tid < 192) b2s[tid - 128] = b2[tid - 128];
    else if (tid < 256) w3s[tid - 192] = W3[2 * H2_ + (tid - 192)];
    if (tid == 0) { scl[0] = *a1p; scl[1] = *a2p; scl[2] = b3[2]; }

    {
        const int row = tid >> 2;
        const int q   = tid & 3;
        const float* src = W1 + (size_t)row * GRUH;
        #pragma unroll
        for (int kk = 0; kk < 4; ++kk) {
            const int kt = q * 4 + kk;
            const float4* s4 = (const float4*)(src + kt * 16);
            float4 f0 = s4[0], f1 = s4[1], f2 = s4[2], f3 = s4[3];
            uint32_t h[8], l[8];
            split2(f0.x, f0.y, h[0], l[0]); split2(f0.z, f0.w, h[1], l[1]);
            split2(f1.x, f1.y, h[2], l[2]); split2(f1.z, f1.w, h[3], l[3]);
            split2(f2.x, f2.y, h[4], l[4]); split2(f2.z, f2.w, h[5], l[5]);
            split2(f3.x, f3.y, h[6], l[6]); split2(f3.z, f3.w, h[7], l[7]);
            uint4* g = w1q + row * W1_GSTRIDE + kt * 4;
            #pragma unroll
            for (int t = 0; t < 4; ++t)
                g[t] = make_uint4(h[t], h[t + 4], l[t], l[t + 4]);
        }
    }
    {
        const int row = tid >> 3;
        const int kt  = tid & 7;
        const float4* s4 = (const float4*)(W2 + (size_t)row * H1_ + kt * 16);
        float4 f0 = s4[0], f1 = s4[1], f2 = s4[2], f3 = s4[3];
        uint32_t h[8], l[8];
        split2(f0.x, f0.y, h[0], l[0]); split2(f0.z, f0.w, h[1], l[1]);
        split2(f1.x, f1.y, h[2], l[2]); split2(f1.z, f1.w, h[3], l[3]);
        split2(f2.x, f2.y, h[4], l[4]); split2(f2.z, f2.w, h[5], l[5]);
        split2(f3.x, f3.y, h[6], l[6]); split2(f3.z, f3.w, h[7], l[7]);
        uint4* g = w2q + row * W2_GSTRIDE + kt * 4;
        #pragma unroll
        for (int t = 0; t < 4; ++t)
            g[t] = make_uint4(h[t], h[t + 4], l[t], l[t + 4]);
    }
    __syncthreads();

    const int wid_m  = wid >> 1;
    const int nhalf  = wid & 1;
    const float* xr0  = X + (size_t)(m0 + wid_m * 32 + grp) * GRUH;
    const float* xr8  = xr0 + 8  * GRUH;
    const float* xr16 = xr0 + 16 * GRUH;
    const float* xr24 = xr0 + 24 * GRUH;

    float acc[2][8][4];
    #pragma unroll
    for (int t = 0; t < 2; ++t)
        #pragma unroll
        for (int nt = 0; nt < 8; ++nt)
            #pragma unroll
            for (int j = 0; j < 4; ++j) acc[t][nt][j] = 0.0f;

    float2 c00, c10, c20, c30, c01, c11, c21, c31;
    {
        const int k0 = tig * 2;
        c00 = *(const float2*)(xr0  + k0);  c01 = *(const float2*)(xr0  + k0 + 8);
        c10 = *(const float2*)(xr8  + k0);  c11 = *(const float2*)(xr8  + k0 + 8);
        c20 = *(const float2*)(xr16 + k0);  c21 = *(const float2*)(xr16 + k0 + 8);
        c30 = *(const float2*)(xr24 + k0);  c31 = *(const float2*)(xr24 + k0 + 8);
    }

    #pragma unroll 1
    for (int kt = 0; kt < 16; ++kt) {
        uint32_t ah0[4], al0[4], ah1[4], al1[4];
        split2(c00.x, c00.y, ah0[0], al0[0]);
        split2(c10.x, c10.y, ah0[1], al0[1]);
        split2(c01.x, c01.y, ah0[2], al0[2]);
        split2(c11.x, c11.y, ah0[3], al0[3]);
        split2(c20.x, c20.y, ah1[0], al1[0]);
        split2(c30.x, c30.y, ah1[1], al1[1]);
        split2(c21.x, c21.y, ah1[2], al1[2]);
        split2(c31.x, c31.y, ah1[3], al1[3]);

        {
            const int ktn = (kt < 15) ? kt + 1 : 15;
            const int k0 = ktn * 16 + tig * 2;
            c00 = *(const float2*)(xr0  + k0);  c01 = *(const float2*)(xr0  + k0 + 8);
            c10 = *(const float2*)(xr8  + k0);  c11 = *(const float2*)(xr8  + k0 + 8);
            c20 = *(const float2*)(xr16 + k0);  c21 = *(const float2*)(xr16 + k0 + 8);
            c30 = *(const float2*)(xr24 + k0);  c31 = *(const float2*)(xr24 + k0 + 8);
        }

        const uint4* base = w1q + (nhalf * 64 + grp) * W1_GSTRIDE + kt * 4 + tig;
        uint4 g = base[0];
        #pragma unroll
        for (int nt = 0; nt < 8; ++nt) {
            // prefetch next granule before consuming current one
            uint4 gn = base[((nt < 7) ? nt + 1 : 7) * 8 * W1_GSTRIDE];
            MMA(acc[0][nt], ah0, g.x, g.y);
            MMA(acc[0][nt], ah0, g.z, g.w);
            MMA(acc[0][nt], al0, g.x, g.y);
            MMA(acc[1][nt], ah1, g.x, g.y);
            MMA(acc[1][nt], ah1, g.z, g.w);
            MMA(acc[1][nt], al1, g.x, g.y);
            g = gn;
        }
    }
    __syncthreads();

    {
        const float A1 = scl[0];
        const int rbase = wid_m * 32 + grp;
        #pragma unroll
        for (int t = 0; t < 2; ++t) {
            const int r = rbase + t * 16;
            #pragma unroll
            for (int nt = 0; nt < 8; ++nt) {
                const int col0 = nhalf * 64 + nt * 8 + tig * 2;
                float v00 = acc[t][nt][0] + b1s[col0];
                float v01 = acc[t][nt][1] + b1s[col0 + 1];
                float v80 = acc[t][nt][2] + b1s[col0];
                float v81 = acc[t][nt][3] + b1s[col0 + 1];
                v00 = (v00 >= 0.0f) ? v00 : A1 * v00;
                v01 = (v01 >= 0.0f) ? v01 : A1 * v01;
                v80 = (v80 >= 0.0f) ? v80 : A1 * v80;
                v81 = (v81 >= 0.0f) ? v81 : A1 * v81;
                uint32_t h0, l0, h8, l8;
                split2(v00, v01, h0, l0);
                split2(v80, v81, h8, l8);
                const int cw = nhalf * 32 + nt * 4 + tig;
                const int w0 = r * H1_WSTRIDE + cw;
                const int w8 = (r + 8) * H1_WSTRIDE + cw;
                h1h[w0] = h0; h1l[w0] = l0;
                h1h[w8] = h8; h1l[w8] = l8;
            }
        }
    }
    __syncthreads();

    float acc2[8][4];
    #pragma unroll
    for (int nt = 0; nt < 8; ++nt)
        #pragma unroll
        for (int j = 0; j < 4; ++j) acc2[nt][j] = 0.0f;

    const int r0w = (wid * 16 + grp) * H1_WSTRIDE;
    const int r8w = (wid * 16 + grp + 8) * H1_WSTRIDE;

    #pragma unroll 1
    for (int kt = 0; kt < 8; ++kt) {
        const int wbase = kt * 8 + tig;
        uint32_t ah[4], al[4];
        ah[0] = h1h[r0w + wbase];     al[0] = h1l[r0w + wbase];
        ah[1] = h1h[r8w + wbase];     al[1] = h1l[r8w + wbase];
        ah[2] = h1h[r0w + wbase + 4]; al[2] = h1l[r0w + wbase + 4];
        ah[3] = h1h[r8w + wbase + 4]; al[3] = h1l[r8w + wbase + 4];
        const uint4* base = w2q + grp * W2_GSTRIDE + kt * 4 + tig;
        uint4 g = base[0];
        #pragma unroll
        for (int nt = 0; nt < 8; ++nt) {
            uint4 gn = base[((nt < 7) ? nt + 1 : 7) * 8 * W2_GSTRIDE];
            MMA(acc2[nt], ah, g.x, g.y);
            MMA(acc2[nt], ah, g.z, g.w);
            MMA(acc2[nt], al, g.x, g.y);
            g = gn;
        }
    }

    {
        const float A2 = scl[1];
        float p0 = 0.0f, p8 = 0.0f;
        #pragma unroll
        for (int nt = 0; nt < 8; ++nt) {
            const int col0 = nt * 8 + tig * 2;
            float v00 = acc2[nt][0] + b2s[col0];
            float v01 = acc2[nt][1] + b2s[col0 + 1];
            float v80 = acc2[nt][2] + b2s[col0];
            float v81 = acc2[nt][3] + b2s[col0 + 1];
            v00 = (v00 >= 0.0f) ? v00 : A2 * v00;
            v01 = (v01 >= 0.0f) ? v01 : A2 * v01;
            v80 = (v80 >= 0.0f) ? v80 : A2 * v80;
            v81 = (v81 >= 0.0f) ? v81 : A2 * v81;
            p0 = fmaf(v00, w3s[col0], fmaf(v01, w3s[col0 + 1], p0));
            p8 = fmaf(v80, w3s[col0], fmaf(v81, w3s[col0 + 1], p8));
        }
        p0 += __shfl_xor_sync(0xffffffffu, p0, 1);
        p0 += __shfl_xor_sync(0xffffffffu, p0, 2);
        p8 += __shfl_xor_sync(0xffffffffu, p8, 1);
        p8 += __shfl_xor_sync(0xffffffffu, p8, 2);
        if (tig == 0) {
            const float bb3 = scl[2];
            float pa = p0 + bb3;
            float pb = p8 + bb3;
            float spa = fmaxf(pa, 0.0f) + log1pf(expf(-fabsf(pa)));
            float spb = fmaxf(pb, 0.0f) + log1pf(expf(-fabsf(pb)));
            float ra = fminf(fmaxf(spa + 1.0f, 1.0f), 20.0f);
            float rb = fminf(fmaxf(spb + 1.0f, 1.0f), 20.0f);
            g_ratio[m0 + wid * 16 + grp]     = ra;
            g_ratio[m0 + wid * 16 + grp + 8] = rb;
        }
    }
}

// =====================================================================
// Kernel B: blocked IIR (8 samples/lane + warp scan per 256 samples)
//   CCHUNK 1280 -> 500 CTAs (3.4 waves); fast divides via __fdividef.
// =====================================================================
#define CCHUNK 1280
#define CWARM  256
#define C_PB   (N_ / CCHUNK)    // 250 chunks per batch

__device__ __forceinline__ float interp_ratio(const float* __restrict__ rb, int n)
{
    float src = ((float)n + 0.5f) * 0.0125f - 0.5f;
    src = fminf(fmaxf(src, 0.0f), 3999.0f);
    float f0 = floorf(src);
    int   i0 = (int)f0;
    int   i1 = min(i0 + 1, 3999);
    float w  = src - f0;
    return rb[i0] * (1.0f - w) + rb[i1] * w;
}
__device__ __forceinline__ float gain_of(float x, float thr, float ratio)
{
    float env = fabsf(x);
    float gr  = (env > thr) ? (thr + __fdividef(env - thr, ratio)) : env;
    float g   = __fdividef(gr, env + 1e-8f);
    return fminf(fmaxf(g, 0.1f), 2.0f);
}

__global__ __launch_bounds__(256)
void compress_kernel(const float* __restrict__ enh,
                     const float* __restrict__ noisy,
                     float* __restrict__ out)
{
    const int w    = (blockIdx.x * blockDim.x + threadIdx.x) >> 5;
    const int lane = threadIdx.x & 31;
    const int b     = w / C_PB;
    const int chunk = w % C_PB;
    const int t0    = chunk * CCHUNK;
    const int start = (chunk == 0) ? 0 : (t0 - CWARM);

    const float* eb = enh   + (size_t)b * N_;
    const float* nb = noisy + (size_t)b * N_;
    float*       ob = out   + (size_t)b * N_;
    const float* rb = g_ratio + b * T_;

    const float q   = 0.43046721f;                    // 0.9^8
    const float qi  = powf(q, (float)lane);           // q^lane
    const float q32 = 1.9342813113834067e-12f;        // 0.9^256

    float s_in_e, s_in_r;
    {
        float e  = eb[start];
        float nn = nb[start];
        float ratio = interp_ratio(rb, start);
        s_in_e = gain_of(e, 0.3f, ratio);
        s_in_r = gain_of(nn - e, 0.1f, ratio * 0.5f);
    }

    float mx_out = 0.0f, mx_enh = 0.0f;
    const int nend = t0 + CCHUNK;

    #pragma unroll 1
    for (int g0 = start; g0 < nend; g0 += 256) {
        const int n0 = g0 + lane * 8;
        float4 e0 = *(const float4*)(eb + n0);
        float4 e1 = *(const float4*)(eb + n0 + 4);
        float4 x0 = *(const float4*)(nb + n0);
        float4 x1 = *(const float4*)(nb + n0 + 4);
        float e[8] = {e0.x, e0.y, e0.z, e0.w, e1.x, e1.y, e1.z, e1.w};
        float x[8] = {x0.x, x0.y, x0.z, x0.w, x1.x, x1.y, x1.z, x1.w};

        float r[8], le[8], lr[8];
        float se = 0.0f, sr = 0.0f;
        #pragma unroll
        for (int j = 0; j < 8; ++j) {
            r[j] = x[j] - e[j];
            float ratio = interp_ratio(rb, n0 + j);
            float ge = gain_of(e[j], 0.3f, ratio);
            float gr = gain_of(r[j], 0.1f, ratio * 0.5f);
            se = fmaf(0.9f, se, 0.1f * ge);  le[j] = se;
            sr = fmaf(0.9f, sr, 0.1f * gr);  lr[j] = sr;
        }

        float Ie = se, Ir = sr, t;
        t = __shfl_up_sync(0xffffffffu, Ie, 1);  if (lane >= 1)  Ie = fmaf(0.43046721f,            t, Ie);
        t = __shfl_up_sync(0xffffffffu, Ir, 1);  if (lane >= 1)  Ir = fmaf(0.43046721f,            t, Ir);
        t = __shfl_up_sync(0xffffffffu, Ie, 2);  if (lane >= 2)  Ie = fmaf(0.1853020188851841f,    t, Ie);
        t = __shfl_up_sync(0xffffffffu, Ir, 2);  if (lane >= 2)  Ir = fmaf(0.1853020188851841f,    t, Ir);
        t = __shfl_up_sync(0xffffffffu, Ie, 4);  if (lane >= 4)  Ie = fmaf(0.03433683820292512f,   t, Ie);
        t = __shfl_up_sync(0xffffffffu, Ir, 4);  if (lane >= 4)  Ir = fmaf(0.03433683820292512f,   t, Ir);
        t = __shfl_up_sync(0xffffffffu, Ie, 8);  if (lane >= 8)  Ie = fmaf(0.001179018457773862f,  t, Ie);
        t = __shfl_up_sync(0xffffffffu, Ir, 8);  if (lane >= 8)  Ir = fmaf(0.001179018457773862f,  t, Ir);
        t = __shfl_up_sync(0xffffffffu, Ie, 16); if (lane >= 16) Ie = fmaf(1.390084523771456e-06f, t, Ie);
        t = __shfl_up_sync(0xffffffffu, Ir, 16); if (lane >= 16) Ir = fmaf(1.390084523771456e-06f, t, Ir);

        float ce = __shfl_up_sync(0xffffffffu, Ie, 1); if (lane == 0) ce = 0.0f;
        float cr = __shfl_up_sync(0xffffffffu, Ir, 1); if (lane == 0) cr = 0.0f;
        ce = fmaf(qi, s_in_e, ce);
        cr = fmaf(qi, s_in_r, cr);

        float Ie31 = __shfl_sync(0xffffffffu, Ie, 31);
        float Ir31 = __shfl_sync(0xffffffffu, Ir, 31);
        s_in_e = fmaf(q32, s_in_e, Ie31);
        s_in_r = fmaf(q32, s_in_r, Ir31);

        if (g0 >= t0) {
            const float d[8] = {0.9f, 0.81f, 0.729f, 0.6561f,
                                0.59049f, 0.531441f, 0.4782969f, 0.43046721f};
            float o[8];
            #pragma unroll
            for (int j = 0; j < 8; ++j) {
                float sej = fmaf(d[j], ce, le[j]);
                float srj = fmaf(d[j], cr, lr[j]);
                o[j] = fmaf(sej, e[j], 0.1f * (srj * r[j]));
                mx_out = fmaxf(mx_out, fabsf(o[j]));
                mx_enh = fmaxf(mx_enh, fabsf(e[j]));
            }
            *(float4*)(ob + n0)     = make_float4(o[0], o[1], o[2], o[3]);
            *(float4*)(ob + n0 + 4) = make_float4(o[4], o[5], o[6], o[7]);
        }
    }

    #pragma unroll
    for (int off = 16; off > 0; off >>= 1) {
        mx_out = fmaxf(mx_out, __shfl_xor_sync(0xffffffffu, mx_out, off));
        mx_enh = fmaxf(mx_enh, __shfl_xor_sync(0xffffffffu, mx_enh, off));
    }
    if (lane == 0) {
        atomicMax(&g_max_out_i, __float_as_int(mx_out));
        atomicMax(&g_max_enh_i, __float_as_int(mx_enh));
    }
}

// =====================================================================
// Kernel C: normalize
// =====================================================================
__global__ __launch_bounds__(256)
void scale_kernel(float* __restrict__ out)
{
    const float mo = __int_as_float(g_max_out_i);
    const float me = __int_as_float(g_max_enh_i);
    const float s  = me / (mo + 1e-8f);
    const int i = blockIdx.x * blockDim.x + threadIdx.x;
    const int n4 = (B_ * N_) / 4;
    if (i < n4) {
        float4* o4 = (float4*)out;
        float4 v = o4[i];
        v.x *= s; v.y *= s; v.z *= s; v.w *= s;
        o4[i] = v;
    }
}

// =====================================================================
extern "C" void kernel_launch(void* const* d_in, const int* in_sizes, int n_in,
                              void* d_out, int out_size)
{
    const float* gru   = (const float*)d_in[0];
    const float* enh   = (const float*)d_in[1];
    const float* noisy = (const float*)d_in[2];
    const float* W1    = (const float*)d_in[3];
    const float* b1    = (const float*)d_in[4];
    const float* a1    = (const float*)d_in[5];
    const float* W2    = (const float*)d_in[6];
    const float* b2    = (const float*)d_in[7];
    const float* a2    = (const float*)d_in[8];
    const float* W3    = (const float*)d_in[9];
    const float* b3    = (const float*)d_in[10];
    float* out = (float*)d_out;

    cudaFuncSetAttribute(mlp_mma_kernel, cudaFuncAttributeMaxDynamicSharedMemorySize, MLP_SMEM);

    mlp_mma_kernel<<<M_ / TOK, 512, MLP_SMEM>>>(gru, W1, b1, a1, W2, b2, a2, W3, b3);
    compress_kernel<<<(B_ * C_PB) / 8, 256>>>(enh, noisy, out);   // 4000 warps
    scale_kernel<<<((B_ * N_ / 4) + 255) / 256, 256>>>(out);
}